// round 11
// baseline (speedup 1.0000x reference)
#include <cuda_runtime.h>
#include <math.h>
#include <stdint.h>

#define D_MODEL 512
#define N_HEADS 8
#define D_KK    64
#define D_FF    2048
#define T_SEQ   2048
#define B_BATCH 2
#define BT      (B_BATCH * T_SEQ)
#define BH      (B_BATCH * N_HEADS)

#define OUT_ELEMS  ((size_t)BT * D_MODEL)
#define ATTN_ELEMS ((size_t)BH * T_SEQ * T_SEQ)

#define EPI_BIAS   0
#define EPI_RELU   1
#define EPI_QKV    2

#define LOG2E 1.4426950408889634f

/* ---------------- scratch ------------------------------------------------- */
__device__ float g_q[BH * T_SEQ * D_KK];
__device__ float g_k[BH * T_SEQ * D_KK];
__device__ float g_v[BH * T_SEQ * D_KK];
__device__ float g_ctx[BT * D_MODEL];
__device__ float g_tmp[BT * D_MODEL];
__device__ float g_h[BT * D_MODEL];
__device__ float g_ffn1[BT * D_FF];
__device__ float g_psum[(size_t)BH * T_SEQ * 32];
__device__ float g_attn_scratch[BH * (size_t)T_SEQ * T_SEQ];

/* ---------------- helpers ------------------------------------------------- */
/* tf32 operand: HMMA reads the top bits; raw fp32 bits = RZ-truncated tf32. */
__device__ __forceinline__ uint32_t f2tf(float f) { return __float_as_uint(f); }

__device__ __forceinline__ float ex2(float x) {
    float r;
    asm("ex2.approx.f32 %0, %1;" : "=f"(r) : "f"(x));
    return r;
}
__device__ __forceinline__ void mma8(float c[4], uint32_t a0, uint32_t a1,
                                     uint32_t a2, uint32_t a3,
                                     uint32_t b0, uint32_t b1) {
    asm volatile(
        "mma.sync.aligned.m16n8k8.row.col.f32.tf32.tf32.f32 "
        "{%0,%1,%2,%3}, {%4,%5,%6,%7}, {%8,%9}, {%0,%1,%2,%3};"
        : "+f"(c[0]), "+f"(c[1]), "+f"(c[2]), "+f"(c[3])
        : "r"(a0), "r"(a1), "r"(a2), "r"(a3), "r"(b0), "r"(b1));
}
__device__ __forceinline__ void cp16(float* sdst, const float* gsrc) {
    uint32_t s = (uint32_t)__cvta_generic_to_shared(sdst);
    asm volatile("cp.async.cg.shared.global [%0], [%1], 16;" :: "r"(s), "l"(gsrc));
}
__device__ __forceinline__ float warp_sum(float v) {
    #pragma unroll
    for (int o = 16; o > 0; o >>= 1) v += __shfl_xor_sync(0xffffffffu, v, o);
    return v;
}

/* ---------------- cp.async double-buffered tf32 GEMM (R8 shapes) ---------- */
template <int BM, int EPI>
__global__ __launch_bounds__(256) void mma_gemm(
    const float* __restrict__ A,
    const float* __restrict__ B0, const float* __restrict__ B1, const float* __restrict__ B2,
    const float* __restrict__ bias0, const float* __restrict__ bias1, const float* __restrict__ bias2,
    float* __restrict__ C0, float* __restrict__ C1, float* __restrict__ C2,
    int M, int N, int K, int lda, int ldb, int ldc)
{
    constexpr int KT  = 32;
    constexpr int SA  = KT + 4;                  /* 36  */
    constexpr int SBk = 128 + 8;                 /* 136 */
    constexpr int A_ELE = BM * SA;
    constexpr int B_ELE = KT * SBk;
    constexpr int STG = A_ELE + B_ELE;
    constexpr int AN = (BM == 128) ? 8 : 4;

    extern __shared__ float smem[];

    const int tid = threadIdx.x;
    const int lane = tid & 31, wid = tid >> 5;
    const int z = blockIdx.z;
    const float* B    = (z == 0) ? B0 : (z == 1) ? B1 : B2;
    const float* bias = (z == 0) ? bias0 : (z == 1) ? bias1 : bias2;
    float* C          = (z == 0) ? C0 : (z == 1) ? C1 : C2;

    const int bm = blockIdx.y * BM;
    const int bn = blockIdx.x * 128;
    const int mb = (BM == 128) ? (wid & 3) * 32 : (wid & 1) * 32;
    const int nb = (BM == 128) ? (wid >> 2) * 64 : (wid >> 1) * 32;

    float acc[2][AN][4];
    #pragma unroll
    for (int i = 0; i < 2; i++)
        #pragma unroll
        for (int j = 0; j < AN; j++)
            #pragma unroll
            for (int r = 0; r < 4; r++) acc[i][j][r] = 0.0f;

    auto issue = [&](int k0, int st) {
        float* As = smem + st * STG;
        float* Bs = As + A_ELE;
        #pragma unroll
        for (int i = 0; i < BM * KT / 1024; i++) {
            int f = tid + i * 256;
            int m = f >> 3, k4 = (f & 7) * 4;
            cp16(&As[m * SA + k4], &A[(size_t)(bm + m) * lda + k0 + k4]);
        }
        #pragma unroll
        for (int i = 0; i < 4; i++) {
            int f = tid + i * 256;
            int kk = f >> 5, n4 = (f & 31) * 4;
            cp16(&Bs[kk * SBk + n4], &B[(size_t)(k0 + kk) * ldb + bn + n4]);
        }
        asm volatile("cp.async.commit_group;" ::: "memory");
    };

    issue(0, 0);
    const int nIter = K / KT;
    for (int it = 0; it < nIter; it++) {
        if (it + 1 < nIter) {
            issue((it + 1) * KT, (it + 1) & 1);
            asm volatile("cp.async.wait_group 1;" ::: "memory");
        } else {
            asm volatile("cp.async.wait_group 0;" ::: "memory");
        }
        __syncthreads();

        float* As = smem + (it & 1) * STG;
        float* Bs = As + A_ELE;
        #pragma unroll
        for (int ks = 0; ks < KT / 8; ks++) {
            uint32_t af[2][4], bf[AN][2];
            #pragma unroll
            for (int am = 0; am < 2; am++)
                #pragma unroll
                for (int j = 0; j < 4; j++)
                    af[am][j] = f2tf(As[(mb + am * 16 + (lane >> 2) + (j & 1) * 8) * SA
                                        + ks * 8 + (lane & 3) + (j >> 1) * 4]);
            #pragma unroll
            for (int an = 0; an < AN; an++)
                #pragma unroll
                for (int j = 0; j < 2; j++)
                    bf[an][j] = f2tf(Bs[(ks * 8 + (lane & 3) + j * 4) * SBk
                                        + nb + an * 8 + (lane >> 2)]);
            #pragma unroll
            for (int am = 0; am < 2; am++)
                #pragma unroll
                for (int an = 0; an < AN; an++)
                    mma8(acc[am][an], af[am][0], af[am][1], af[am][2], af[am][3],
                         bf[an][0], bf[an][1]);
        }
        __syncthreads();
    }

    #pragma unroll
    for (int am = 0; am < 2; am++)
        #pragma unroll
        for (int an = 0; an < AN; an++)
            #pragma unroll
            for (int half = 0; half < 2; half++) {
                int m = bm + mb + am * 16 + (lane >> 2) + half * 8;
                int c = bn + nb + an * 8 + (lane & 3) * 2;
                float v0 = acc[am][an][half * 2 + 0] + bias[c];
                float v1 = acc[am][an][half * 2 + 1] + bias[c + 1];
                if (EPI == EPI_RELU) { v0 = fmaxf(v0, 0.0f); v1 = fmaxf(v1, 0.0f); }
                if (EPI == EPI_QKV) {
                    int bb = m >> 11, t = m & (T_SEQ - 1);
                    int h = c >> 6, d = c & (D_KK - 1);
                    *(float2*)&C[((size_t)((bb * N_HEADS + h) * T_SEQ) + t) * D_KK + d]
                        = make_float2(v0, v1);
                } else {
                    *(float2*)&C[(size_t)m * ldc + c] = make_float2(v0, v1);
                }
            }
}

/* ---------------- scores (per head z): attn <- exp2(QK^T*sc), psums ------- */
__global__ __launch_bounds__(256) void scores_kernel(
    const float* __restrict__ Q, const float* __restrict__ K,
    float* __restrict__ attn, float* __restrict__ psum, int z)
{
    constexpr int S = 68;
    extern __shared__ float sm[];
    float* Qs = sm;              /* [128][68] */
    float* Ks = sm + 128 * S;    /* [128][68] */

    const int tid = threadIdx.x;
    const int lane = tid & 31, wid = tid >> 5;
    const int bm = blockIdx.y * 128;
    const int bn = blockIdx.x * 128;
    Q += (size_t)z * T_SEQ * D_KK;
    K += (size_t)z * T_SEQ * D_KK;

    #pragma unroll
    for (int i = 0; i < 8; i++) {
        int f = tid + i * 256;
        int m = f >> 4, k4 = (f & 15) * 4;
        cp16(&Qs[m * S + k4], &Q[(size_t)(bm + m) * D_KK + k4]);
        cp16(&Ks[m * S + k4], &K[(size_t)(bn + m) * D_KK + k4]);
    }
    asm volatile("cp.async.commit_group;" ::: "memory");
    asm volatile("cp.async.wait_group 0;" ::: "memory");
    __syncthreads();

    const int mb = (wid & 3) * 32;
    const int nwarp = wid >> 2;
    const int nb = nwarp * 64;

    float acc[2][8][4];
    #pragma unroll
    for (int i = 0; i < 2; i++)
        #pragma unroll
        for (int j = 0; j < 8; j++)
            #pragma unroll
            for (int r = 0; r < 4; r++) acc[i][j][r] = 0.0f;

    #pragma unroll
    for (int ks = 0; ks < 8; ks++) {
        uint32_t af[2][4], bf[8][2];
        #pragma unroll
        for (int am = 0; am < 2; am++)
            #pragma unroll
            for (int j = 0; j < 4; j++)
                af[am][j] = f2tf(Qs[(mb + am * 16 + (lane >> 2) + (j & 1) * 8) * S
                                    + ks * 8 + (lane & 3) + (j >> 1) * 4]);
        #pragma unroll
        for (int an = 0; an < 8; an++)
            #pragma unroll
            for (int j = 0; j < 2; j++)
                bf[an][j] = f2tf(Ks[(nb + an * 8 + (lane >> 2)) * S
                                    + ks * 8 + (lane & 3) + j * 4]);
        #pragma unroll
        for (int am = 0; am < 2; am++)
            #pragma unroll
            for (int an = 0; an < 8; an++)
                mma8(acc[am][an], af[am][0], af[am][1], af[am][2], af[am][3],
                     bf[an][0], bf[an][1]);
    }

    const float sc = 0.125f * LOG2E;
    float* Cz = attn + (size_t)z * T_SEQ * T_SEQ;
    #pragma unroll
    for (int am = 0; am < 2; am++)
        #pragma unroll
        for (int half = 0; half < 2; half++) {
            int m = bm + mb + am * 16 + (lane >> 2) + half * 8;
            float rs = 0.0f;
            #pragma unroll
            for (int an = 0; an < 8; an++) {
                int c = bn + nb + an * 8 + (lane & 3) * 2;
                float e0 = ex2(acc[am][an][half * 2 + 0] * sc);
                float e1 = ex2(acc[am][an][half * 2 + 1] * sc);
                *(float2*)&Cz[(size_t)m * T_SEQ + c] = make_float2(e0, e1);
                rs += e0 + e1;
            }
            rs += __shfl_xor_sync(0xffffffffu, rs, 1);
            rs += __shfl_xor_sync(0xffffffffu, rs, 2);
            if ((lane & 3) == 0)
                psum[((size_t)z * T_SEQ + m) * 32 + blockIdx.x * 2 + nwarp] = rs;
        }
}

/* ---------------- per-head fused psum-reduce + normalize + P@V ------------ */
__global__ __launch_bounds__(256, 3) void attn_pv_kernel(
    float* __restrict__ attn, const float* __restrict__ V,
    const float* __restrict__ psum, float* __restrict__ ctx, int z)
{
    constexpr int KT = 64;
    constexpr int BM = 64;
    constexpr int SA = 68;     /* [m=64][k=64]+4 */
    constexpr int SV = 72;     /* [k=64][n=64]+8 */
    constexpr int A_ELE = BM * SA;             /* 4352 */
    constexpr int STG = A_ELE + KT * SV;       /* 8960 */
    extern __shared__ float sm[];
    float* invs = sm + 2 * STG;

    const int tid = threadIdx.x;
    const int lane = tid & 31, wid = tid >> 5;
    const int bm = blockIdx.x * BM;
    attn += (size_t)z * T_SEQ * T_SEQ;
    V    += (size_t)z * T_SEQ * D_KK;

    auto issue = [&](int k0, int st) {
        float* As = sm + st * STG;
        float* Vs = As + A_ELE;
        #pragma unroll
        for (int i = 0; i < 4; i++) {
            int f = tid + i * 256;
            int m = f >> 4, k4 = (f & 15) * 4;
            cp16(&As[m * SA + k4], &attn[(size_t)(bm + m) * T_SEQ + k0 + k4]);
        }
        #pragma unroll
        for (int i = 0; i < 4; i++) {
            int f = tid + i * 256;
            int kk = f >> 4, c4 = (f & 15) * 4;
            cp16(&Vs[kk * SV + c4], &V[(size_t)(k0 + kk) * D_KK + c4]);
        }
        asm volatile("cp.async.commit_group;" ::: "memory");
    };

    issue(0, 0);

    /* reduce this stripe's psums -> invs (CTA exclusively owns rows) */
    if (tid < BM) {
        const float4* p = (const float4*)(psum + ((size_t)z * T_SEQ + bm + tid) * 32);
        float s = 0.0f;
        #pragma unroll
        for (int i = 0; i < 8; i++) {
            float4 v = p[i];
            s += v.x + v.y + v.z + v.w;
        }
        invs[tid] = 1.0f / s;
    }
    __syncthreads();

    const int mb = (wid & 1) * 32;
    const int nb = (wid >> 1) * 16;

    float acc[2][2][4];
    #pragma unroll
    for (int i = 0; i < 2; i++)
        #pragma unroll
        for (int j = 0; j < 2; j++)
            #pragma unroll
            for (int r = 0; r < 4; r++) acc[i][j][r] = 0.0f;

    const int nIter = T_SEQ / KT;   /* 32 */
    for (int it = 0; it < nIter; it++) {
        if (it + 1 < nIter) {
            issue((it + 1) * KT, (it + 1) & 1);
            asm volatile("cp.async.wait_group 1;" ::: "memory");
        } else {
            asm volatile("cp.async.wait_group 0;" ::: "memory");
        }
        __syncthreads();

        float* As = sm + (it & 1) * STG;
        float* Vs = As + A_ELE;

        #pragma unroll
        for (int ks = 0; ks < KT / 8; ks++) {
            uint32_t af[2][4], bf[2][2];
            #pragma unroll
            for (int am = 0; am < 2; am++)
                #pragma unroll
                for (int j = 0; j < 4; j++)
                    af[am][j] = f2tf(As[(mb + am * 16 + (lane >> 2) + (j & 1) * 8) * SA
                                        + ks * 8 + (lane & 3) + (j >> 1) * 4]);
            #pragma unroll
            for (int an = 0; an < 2; an++)
                #pragma unroll
                for (int j = 0; j < 2; j++)
                    bf[an][j] = f2tf(Vs[(ks * 8 + (lane & 3) + j * 4) * SV
                                        + nb + an * 8 + (lane >> 2)]);
            #pragma unroll
            for (int am = 0; am < 2; am++)
                #pragma unroll
                for (int an = 0; an < 2; an++)
                    mma8(acc[am][an], af[am][0], af[am][1], af[am][2], af[am][3],
                         bf[an][0], bf[an][1]);
        }

        /* normalized in-place attn write from smem (coalesced STG.128) */
        #pragma unroll
        for (int i = 0; i < 4; i++) {
            int f = tid + i * 256;
            int m = f >> 4, k4 = (f & 15) * 4;
            float4 v = *(const float4*)&As[m * SA + k4];
            float iv = invs[m];
            v.x *= iv; v.y *= iv; v.z *= iv; v.w *= iv;
            *(float4*)&attn[(size_t)(bm + m) * T_SEQ + it * KT + k4] = v;
        }
        __syncthreads();
    }

    const int b = z >> 3, h = z & 7;
    float* Cz = ctx + (size_t)b * T_SEQ * D_MODEL + h * D_KK;
    #pragma unroll
    for (int am = 0; am < 2; am++)
        #pragma unroll
        for (int an = 0; an < 2; an++)
            #pragma unroll
            for (int half = 0; half < 2; half++) {
                int mr = mb + am * 16 + (lane >> 2) + half * 8;
                int c = nb + an * 8 + (lane & 3) * 2;
                float iv = invs[mr];
                *(float2*)&Cz[(size_t)(bm + mr) * D_MODEL + c]
                    = make_float2(acc[am][an][half * 2 + 0] * iv,
                                  acc[am][an][half * 2 + 1] * iv);
            }
}

/* ---------------- fused residual add + LayerNorm ------------------------- */
__global__ __launch_bounds__(128) void add_ln_kernel(
    const float* __restrict__ X, const float* __restrict__ Y,
    const float* __restrict__ g, const float* __restrict__ b,
    float* __restrict__ O)
{
    const int tid = threadIdx.x;
    const size_t base = (size_t)blockIdx.x * D_MODEL + tid * 4;
    float4 xv = *(const float4*)&X[base];
    float4 yv = *(const float4*)&Y[base];
    float4 v = make_float4(xv.x + yv.x, xv.y + yv.y, xv.z + yv.z, xv.w + yv.w);

    float s  = v.x + v.y + v.z + v.w;
    float ss = v.x * v.x + v.y * v.y + v.z * v.z + v.w * v.w;
    s = warp_sum(s);
    ss = warp_sum(ss);

    __shared__ float r1[4], r2[4];
    const int wid = tid >> 5, lane = tid & 31;
    if (lane == 0) { r1[wid] = s; r2[wid] = ss; }
    __syncthreads();
    if (tid == 0) {
        float a = 0.0f, c = 0.0f;
        #pragma unroll
        for (int i = 0; i < 4; i++) { a += r1[i]; c += r2[i]; }
        r1[0] = a; r2[0] = c;
    }
    __syncthreads();
    const float mu  = r1[0] * (1.0f / 512.0f);
    const float var = r2[0] * (1.0f / 512.0f) - mu * mu;
    const float rs  = rsqrtf(var + 1e-5f);

    float4 gv = *(const float4*)&g[tid * 4];
    float4 bv = *(const float4*)&b[tid * 4];
    float4 o;
    o.x = (v.x - mu) * rs * gv.x + bv.x;
    o.y = (v.y - mu) * rs * gv.y + bv.y;
    o.z = (v.z - mu) * rs * gv.z + bv.z;
    o.w = (v.w - mu) * rs * gv.w + bv.w;
    *(float4*)&O[base] = o;
}

/* ---------------- launch -------------------------------------------------- */
#define SMEM_G128   71680   /* 2*(128*36 + 32*136)*4 */
#define SMEM_G64    53248   /* 2*( 64*36 + 32*136)*4 */
#define SMEM_SCORES 69632   /* 2*128*68*4 */
#define SMEM_PV     71936   /* (2*8960 + 64)*4 */

extern "C" void kernel_launch(void* const* d_in, const int* in_sizes, int n_in,
                              void* d_out, int out_size)
{
    const float* x     = (const float*)d_in[0];
    const float* wq_w  = (const float*)d_in[1];
    const float* wq_b  = (const float*)d_in[2];
    const float* wk_w  = (const float*)d_in[3];
    const float* wk_b  = (const float*)d_in[4];
    const float* wv_w  = (const float*)d_in[5];
    const float* wv_b  = (const float*)d_in[6];
    const float* wo_w  = (const float*)d_in[7];
    const float* wo_b  = (const float*)d_in[8];
    const float* ln1_g = (const float*)d_in[9];
    const float* ln1_b = (const float*)d_in[10];
    const float* fc1_w = (const float*)d_in[11];
    const float* fc1_b = (const float*)d_in[12];
    const float* fc2_w = (const float*)d_in[13];
    const float* fc2_b = (const float*)d_in[14];
    const float* ln2_g = (const float*)d_in[15];
    const float* ln2_b = (const float*)d_in[16];

    float* out = (float*)d_out;

    float *pq, *pk, *pv, *pctx, *ptmp, *ph, *pffn1, *ppsum;
    cudaGetSymbolAddress((void**)&pq,    g_q);
    cudaGetSymbolAddress((void**)&pk,    g_k);
    cudaGetSymbolAddress((void**)&pv,    g_v);
    cudaGetSymbolAddress((void**)&pctx,  g_ctx);
    cudaGetSymbolAddress((void**)&ptmp,  g_tmp);
    cudaGetSymbolAddress((void**)&ph,    g_h);
    cudaGetSymbolAddress((void**)&pffn1, g_ffn1);
    cudaGetSymbolAddress((void**)&ppsum, g_psum);

    float* attn;
    if ((size_t)out_size >= OUT_ELEMS + ATTN_ELEMS) {
        attn = out + OUT_ELEMS;
    } else {
        cudaGetSymbolAddress((void**)&attn, g_attn_scratch);
    }

    cudaFuncSetAttribute(mma_gemm<64, EPI_QKV>,
                         cudaFuncAttributeMaxDynamicSharedMemorySize, SMEM_G64);
    cudaFuncSetAttribute(mma_gemm<64, EPI_BIAS>,
                         cudaFuncAttributeMaxDynamicSharedMemorySize, SMEM_G64);
    cudaFuncSetAttribute(mma_gemm<128, EPI_RELU>,
                         cudaFuncAttributeMaxDynamicSharedMemorySize, SMEM_G128);
    cudaFuncSetAttribute(scores_kernel,
                         cudaFuncAttributeMaxDynamicSharedMemorySize, SMEM_SCORES);
    cudaFuncSetAttribute(attn_pv_kernel,
                         cudaFuncAttributeMaxDynamicSharedMemorySize, SMEM_PV);

    /* second stream + events for the per-head scores->PV pipeline.
     * Created fresh each call (kernel_launch is invoked only a handful of
     * times; graph REPLAYS do not run host code). Not destroyed: events
     * recorded during capture must outlive capture. */
    cudaStream_t s1;
    cudaStreamCreateWithFlags(&s1, cudaStreamNonBlocking);
    cudaEvent_t evS[BH], evJ;
    for (int i = 0; i < BH; i++)
        cudaEventCreateWithFlags(&evS[i], cudaEventDisableTiming);
    cudaEventCreateWithFlags(&evJ, cudaEventDisableTiming);

    /* QKV: one launch (R8 shape: 64x128 tiles, grid 768) */
    mma_gemm<64, EPI_QKV><<<dim3(4, 64, 3), 256, SMEM_G64>>>(
        x, wq_w, wk_w, wv_w, wq_b, wk_b, wv_b, pq, pk, pv,
        BT, D_MODEL, D_MODEL, D_MODEL, D_MODEL, D_MODEL);

    /* attention pipeline: scores(z) on stream 0; PV(z) on s1 right behind it
     * (expS(z)=16MB still L2-resident; PV(z) overlaps scores(z+1)). */
    for (int z = 0; z < BH; z++) {
        scores_kernel<<<dim3(16, 16), 256, SMEM_SCORES>>>(pq, pk, attn, ppsum, z);
        cudaEventRecord(evS[z], 0);
        cudaStreamWaitEvent(s1, evS[z], 0);
        attn_pv_kernel<<<T_SEQ / 64, 256, SMEM_PV, s1>>>(attn, pv, ppsum, pctx, z);
    }
    cudaEventRecord(evJ, s1);
    cudaStreamWaitEvent(0, evJ, 0);

    /* output projection + LN1 */
    mma_gemm<64, EPI_BIAS><<<dim3(4, 64, 1), 256, SMEM_G64>>>(
        pctx, wo_w, wo_w, wo_w, wo_b, wo_b, wo_b, ptmp, ptmp, ptmp,
        BT, D_MODEL, D_MODEL, D_MODEL, D_MODEL, D_MODEL);
    add_ln_kernel<<<BT, 128>>>(x, ptmp, ln1_g, ln1_b, ph);

    /* FFN + LN2 (R8 shapes: FC1 128x128, FC2 64x128) */
    mma_gemm<128, EPI_RELU><<<dim3(16, 32, 1), 256, SMEM_G128>>>(
        ph, fc1_w, fc1_w, fc1_w, fc1_b, fc1_b, fc1_b, pffn1, pffn1, pffn1,
        BT, D_FF, D_MODEL, D_MODEL, D_FF, D_FF);
    mma_gemm<64, EPI_BIAS><<<dim3(4, 64, 1), 256, SMEM_G64>>>(
        pffn1, fc2_w, fc2_w, fc2_w, fc2_b, fc2_b, fc2_b, ptmp, ptmp, ptmp,
        BT, D_MODEL, D_FF, D_FF, D_MODEL, D_MODEL);
    add_ln_kernel<<<BT, 128>>>(ph, ptmp, ln2_g, ln2_b, out);
}

// round 12
// speedup vs baseline: 1.2840x; 1.2840x over previous
#include <cuda_runtime.h>
#include <math.h>
#include <stdint.h>

#define D_MODEL 512
#define N_HEADS 8
#define D_KK    64
#define D_FF    2048
#define T_SEQ   2048
#define B_BATCH 2
#define BT      (B_BATCH * T_SEQ)
#define BH      (B_BATCH * N_HEADS)

#define OUT_ELEMS  ((size_t)BT * D_MODEL)
#define ATTN_ELEMS ((size_t)BH * T_SEQ * T_SEQ)

#define EPI_BIAS   0
#define EPI_RELU   1
#define EPI_QKV    2

#define LOG2E 1.4426950408889634f

/* ---------------- scratch ------------------------------------------------- */
__device__ float g_q[BH * T_SEQ * D_KK];
__device__ float g_k[BH * T_SEQ * D_KK];
__device__ float g_v[BH * T_SEQ * D_KK];
__device__ float g_ctx[BT * D_MODEL];
__device__ float g_tmp[BT * D_MODEL];
__device__ float g_h[BT * D_MODEL];
__device__ float g_ffn1[BT * D_FF];
__device__ float g_attn_scratch[BH * (size_t)T_SEQ * T_SEQ];

/* ---------------- helpers ------------------------------------------------- */
/* tf32 operand: HMMA reads the top bits; raw fp32 bits = RZ-truncated tf32. */
__device__ __forceinline__ uint32_t f2tf(float f) { return __float_as_uint(f); }

__device__ __forceinline__ float ex2(float x) {
    float r;
    asm("ex2.approx.f32 %0, %1;" : "=f"(r) : "f"(x));
    return r;
}
__device__ __forceinline__ void mma8(float c[4], uint32_t a0, uint32_t a1,
                                     uint32_t a2, uint32_t a3,
                                     uint32_t b0, uint32_t b1) {
    asm volatile(
        "mma.sync.aligned.m16n8k8.row.col.f32.tf32.tf32.f32 "
        "{%0,%1,%2,%3}, {%4,%5,%6,%7}, {%8,%9}, {%0,%1,%2,%3};"
        : "+f"(c[0]), "+f"(c[1]), "+f"(c[2]), "+f"(c[3])
        : "r"(a0), "r"(a1), "r"(a2), "r"(a3), "r"(b0), "r"(b1));
}
__device__ __forceinline__ void cp16(float* sdst, const float* gsrc) {
    uint32_t s = (uint32_t)__cvta_generic_to_shared(sdst);
    asm volatile("cp.async.cg.shared.global [%0], [%1], 16;" :: "r"(s), "l"(gsrc));
}
__device__ __forceinline__ float warp_sum(float v) {
    #pragma unroll
    for (int o = 16; o > 0; o >>= 1) v += __shfl_xor_sync(0xffffffffu, v, o);
    return v;
}

/* ---------------- cp.async double-buffered tf32 GEMM (R8 shapes) ---------- */
template <int BM, int EPI>
__global__ __launch_bounds__(256) void mma_gemm(
    const float* __restrict__ A,
    const float* __restrict__ B0, const float* __restrict__ B1, const float* __restrict__ B2,
    const float* __restrict__ bias0, const float* __restrict__ bias1, const float* __restrict__ bias2,
    float* __restrict__ C0, float* __restrict__ C1, float* __restrict__ C2,
    int M, int N, int K, int lda, int ldb, int ldc)
{
    constexpr int KT  = 32;
    constexpr int SA  = KT + 4;                  /* 36  */
    constexpr int SBk = 128 + 8;                 /* 136 */
    constexpr int A_ELE = BM * SA;
    constexpr int B_ELE = KT * SBk;
    constexpr int STG = A_ELE + B_ELE;
    constexpr int AN = (BM == 128) ? 8 : 4;

    extern __shared__ float smem[];

    const int tid = threadIdx.x;
    const int lane = tid & 31, wid = tid >> 5;
    const int z = blockIdx.z;
    const float* B    = (z == 0) ? B0 : (z == 1) ? B1 : B2;
    const float* bias = (z == 0) ? bias0 : (z == 1) ? bias1 : bias2;
    float* C          = (z == 0) ? C0 : (z == 1) ? C1 : C2;

    const int bm = blockIdx.y * BM;
    const int bn = blockIdx.x * 128;
    const int mb = (BM == 128) ? (wid & 3) * 32 : (wid & 1) * 32;
    const int nb = (BM == 128) ? (wid >> 2) * 64 : (wid >> 1) * 32;

    float acc[2][AN][4];
    #pragma unroll
    for (int i = 0; i < 2; i++)
        #pragma unroll
        for (int j = 0; j < AN; j++)
            #pragma unroll
            for (int r = 0; r < 4; r++) acc[i][j][r] = 0.0f;

    auto issue = [&](int k0, int st) {
        float* As = smem + st * STG;
        float* Bs = As + A_ELE;
        #pragma unroll
        for (int i = 0; i < BM * KT / 1024; i++) {
            int f = tid + i * 256;
            int m = f >> 3, k4 = (f & 7) * 4;
            cp16(&As[m * SA + k4], &A[(size_t)(bm + m) * lda + k0 + k4]);
        }
        #pragma unroll
        for (int i = 0; i < 4; i++) {
            int f = tid + i * 256;
            int kk = f >> 5, n4 = (f & 31) * 4;
            cp16(&Bs[kk * SBk + n4], &B[(size_t)(k0 + kk) * ldb + bn + n4]);
        }
        asm volatile("cp.async.commit_group;" ::: "memory");
    };

    issue(0, 0);
    const int nIter = K / KT;
    for (int it = 0; it < nIter; it++) {
        if (it + 1 < nIter) {
            issue((it + 1) * KT, (it + 1) & 1);
            asm volatile("cp.async.wait_group 1;" ::: "memory");
        } else {
            asm volatile("cp.async.wait_group 0;" ::: "memory");
        }
        __syncthreads();

        float* As = smem + (it & 1) * STG;
        float* Bs = As + A_ELE;
        #pragma unroll
        for (int ks = 0; ks < KT / 8; ks++) {
            uint32_t af[2][4], bf[AN][2];
            #pragma unroll
            for (int am = 0; am < 2; am++)
                #pragma unroll
                for (int j = 0; j < 4; j++)
                    af[am][j] = f2tf(As[(mb + am * 16 + (lane >> 2) + (j & 1) * 8) * SA
                                        + ks * 8 + (lane & 3) + (j >> 1) * 4]);
            #pragma unroll
            for (int an = 0; an < AN; an++)
                #pragma unroll
                for (int j = 0; j < 2; j++)
                    bf[an][j] = f2tf(Bs[(ks * 8 + (lane & 3) + j * 4) * SBk
                                        + nb + an * 8 + (lane >> 2)]);
            #pragma unroll
            for (int am = 0; am < 2; am++)
                #pragma unroll
                for (int an = 0; an < AN; an++)
                    mma8(acc[am][an], af[am][0], af[am][1], af[am][2], af[am][3],
                         bf[an][0], bf[an][1]);
        }
        __syncthreads();
    }

    #pragma unroll
    for (int am = 0; am < 2; am++)
        #pragma unroll
        for (int an = 0; an < AN; an++)
            #pragma unroll
            for (int half = 0; half < 2; half++) {
                int m = bm + mb + am * 16 + (lane >> 2) + half * 8;
                int c = bn + nb + an * 8 + (lane & 3) * 2;
                float v0 = acc[am][an][half * 2 + 0] + bias[c];
                float v1 = acc[am][an][half * 2 + 1] + bias[c + 1];
                if (EPI == EPI_RELU) { v0 = fmaxf(v0, 0.0f); v1 = fmaxf(v1, 0.0f); }
                if (EPI == EPI_QKV) {
                    int bb = m >> 11, t = m & (T_SEQ - 1);
                    int h = c >> 6, d = c & (D_KK - 1);
                    *(float2*)&C[((size_t)((bb * N_HEADS + h) * T_SEQ) + t) * D_KK + d]
                        = make_float2(v0, v1);
                } else {
                    *(float2*)&C[(size_t)m * ldc + c] = make_float2(v0, v1);
                }
            }
}

/* ---------------- fused attention: one CTA owns a 16-row stripe -----------
 * Phase 1: stream K tiles (64 rows), S = Q@K^T, P = exp2(S*sc) -> smem,
 *          accumulate row sums.
 * Phase 2: inv = 1/rowsum; normalize P in smem; write attn stripe ONCE.
 * Phase 3: stream V tiles; ctx = P @ V from smem.
 * attn HBM traffic: one 268MB write total (vs 804MB in split version).
 */
#define PS 2052   /* P row stride: %32==4 -> conflict-free A-frag loads */

__global__ __launch_bounds__(256) void attn_fused_kernel(
    const float* __restrict__ Q, const float* __restrict__ Kg,
    const float* __restrict__ Vg, float* __restrict__ attn,
    float* __restrict__ ctx)
{
    extern __shared__ float sm[];
    float* P    = sm;                    /* 16 * 2052 = 32832 */
    float* Qs   = P + 16 * PS;           /* 16 * 68   = 1088  */
    float* St   = Qs + 1088;             /* 2 stages * 4608   */
    float* red  = St + 2 * 4608;         /* 8 warps * 16 rows */
    float* invs = red + 128;             /* 16 */

    const int tid = threadIdx.x;
    const int lane = tid & 31, wid = tid >> 5;
    const int r0 = lane >> 2;
    const int stripe = blockIdx.x, z = blockIdx.y;

    const float* Qz = Q + ((size_t)z * T_SEQ + stripe * 16) * D_KK;
    const float* Kz = Kg + (size_t)z * T_SEQ * D_KK;
    const float* Vz = Vg + (size_t)z * T_SEQ * D_KK;
    float* attnz = attn + (size_t)z * T_SEQ * T_SEQ + (size_t)(stripe * 16) * T_SEQ;

    auto issueK = [&](int it, int st) {
        float* Ks = St + st * 4608;
        #pragma unroll
        for (int i = 0; i < 4; i++) {
            int f = tid + i * 256;
            int n = f >> 4, k4 = (f & 15) * 4;
            cp16(&Ks[n * 68 + k4], &Kz[(size_t)(it * 64 + n) * D_KK + k4]);
        }
        asm volatile("cp.async.commit_group;" ::: "memory");
    };
    auto issueV = [&](int it, int st) {
        float* Vs = St + st * 4608;
        #pragma unroll
        for (int i = 0; i < 4; i++) {
            int f = tid + i * 256;
            int kk = f >> 4, c4 = (f & 15) * 4;
            cp16(&Vs[kk * 72 + c4], &Vz[(size_t)(it * 64 + kk) * D_KK + c4]);
        }
        asm volatile("cp.async.commit_group;" ::: "memory");
    };

    /* group 0: Q stripe + K tile 0; group 1: K tile 1 */
    cp16(&Qs[(tid >> 4) * 68 + (tid & 15) * 4],
         &Qz[(size_t)(tid >> 4) * D_KK + (tid & 15) * 4]);
    issueK(0, 0);
    issueK(1, 1);

    asm volatile("cp.async.wait_group 1;" ::: "memory");
    __syncthreads();

    /* hoist Q fragments: 32 regs, reused by every scores tile */
    uint32_t qf[8][4];
    #pragma unroll
    for (int ks = 0; ks < 8; ks++)
        #pragma unroll
        for (int j = 0; j < 4; j++)
            qf[ks][j] = f2tf(Qs[(r0 + (j & 1) * 8) * 68
                                + ks * 8 + (lane & 3) + (j >> 1) * 4]);

    const float sc = 0.125f * LOG2E;
    float rs0 = 0.0f, rs1 = 0.0f;

    /* ---- phase 1: scores + exp into P ---- */
    for (int it = 0; it < 32; it++) {
        if (it == 31) { asm volatile("cp.async.wait_group 0;" ::: "memory"); }
        else          { asm volatile("cp.async.wait_group 1;" ::: "memory"); }
        __syncthreads();

        float* Ks = St + (it & 1) * 4608;
        float acc[4] = {0.0f, 0.0f, 0.0f, 0.0f};
        #pragma unroll
        for (int ks = 0; ks < 8; ks++) {
            uint32_t b0 = f2tf(Ks[(wid * 8 + r0) * 68 + ks * 8 + (lane & 3)]);
            uint32_t b1 = f2tf(Ks[(wid * 8 + r0) * 68 + ks * 8 + (lane & 3) + 4]);
            mma8(acc, qf[ks][0], qf[ks][1], qf[ks][2], qf[ks][3], b0, b1);
        }
        float e0 = ex2(acc[0] * sc);
        float e1 = ex2(acc[1] * sc);
        float e2 = ex2(acc[2] * sc);
        float e3 = ex2(acc[3] * sc);
        int n = it * 64 + wid * 8 + (lane & 3) * 2;
        *(float2*)&P[r0 * PS + n]       = make_float2(e0, e1);
        *(float2*)&P[(r0 + 8) * PS + n] = make_float2(e2, e3);
        rs0 += e0 + e1;
        rs1 += e2 + e3;
        __syncthreads();
        if (it + 2 < 32) issueK(it + 2, it & 1);
    }

    /* prefetch V tiles 0,1 (K buffers free after the final sync above) */
    issueV(0, 0);
    issueV(1, 1);

    /* ---- rowsum reduce -> invs ---- */
    rs0 += __shfl_xor_sync(0xffffffffu, rs0, 1);
    rs0 += __shfl_xor_sync(0xffffffffu, rs0, 2);
    rs1 += __shfl_xor_sync(0xffffffffu, rs1, 1);
    rs1 += __shfl_xor_sync(0xffffffffu, rs1, 2);
    if ((lane & 3) == 0) {
        red[wid * 16 + r0]     = rs0;
        red[wid * 16 + r0 + 8] = rs1;
    }
    __syncthreads();
    if (tid < 16) {
        float s = 0.0f;
        #pragma unroll
        for (int w = 0; w < 8; w++) s += red[w * 16 + tid];
        invs[tid] = 1.0f / s;
    }
    __syncthreads();

    /* ---- phase 2: normalize P in smem + single attn write ---- */
    #pragma unroll
    for (int i = 0; i < 32; i++) {
        int idx = tid + i * 256;
        int m = idx >> 9, c4 = (idx & 511) * 4;
        float4 v = *(const float4*)&P[m * PS + c4];
        float iv = invs[m];
        v.x *= iv; v.y *= iv; v.z *= iv; v.w *= iv;
        *(float4*)&P[m * PS + c4] = v;
        *(float4*)&attnz[(size_t)m * T_SEQ + c4] = v;
    }
    __syncthreads();

    /* ---- phase 3: ctx = P @ V ---- */
    float pacc[4] = {0.0f, 0.0f, 0.0f, 0.0f};
    for (int kt = 0; kt < 32; kt++) {
        if (kt == 31) { asm volatile("cp.async.wait_group 0;" ::: "memory"); }
        else          { asm volatile("cp.async.wait_group 1;" ::: "memory"); }
        __syncthreads();

        float* Vs = St + (kt & 1) * 4608;
        #pragma unroll
        for (int ks = 0; ks < 8; ks++) {
            uint32_t af[4];
            #pragma unroll
            for (int j = 0; j < 4; j++)
                af[j] = f2tf(P[(r0 + (j & 1) * 8) * PS
                               + kt * 64 + ks * 8 + (lane & 3) + (j >> 1) * 4]);
            uint32_t b0 = f2tf(Vs[(ks * 8 + (lane & 3)) * 72 + wid * 8 + r0]);
            uint32_t b1 = f2tf(Vs[(ks * 8 + (lane & 3) + 4) * 72 + wid * 8 + r0]);
            mma8(pacc, af[0], af[1], af[2], af[3], b0, b1);
        }
        __syncthreads();
        if (kt + 2 < 32) issueV(kt + 2, kt & 1);
    }

    const int bb = z >> 3, h = z & 7;
    #pragma unroll
    for (int half = 0; half < 2; half++) {
        int row = stripe * 16 + r0 + half * 8;
        *(float2*)&ctx[((size_t)(bb * T_SEQ) + row) * D_MODEL + h * D_KK
                       + wid * 8 + (lane & 3) * 2]
            = make_float2(pacc[half * 2 + 0], pacc[half * 2 + 1]);
    }
}

/* ---------------- fused residual add + LayerNorm ------------------------- */
__global__ __launch_bounds__(128) void add_ln_kernel(
    const float* __restrict__ X, const float* __restrict__ Y,
    const float* __restrict__ g, const float* __restrict__ b,
    float* __restrict__ O)
{
    const int tid = threadIdx.x;
    const size_t base = (size_t)blockIdx.x * D_MODEL + tid * 4;
    float4 xv = *(const float4*)&X[base];
    float4 yv = *(const float4*)&Y[base];
    float4 v = make_float4(xv.x + yv.x, xv.y + yv.y, xv.z + yv.z, xv.w + yv.w);

    float s  = v.x + v.y + v.z + v.w;
    float ss = v.x * v.x + v.y * v.y + v.z * v.z + v.w * v.w;
    s = warp_sum(s);
    ss = warp_sum(ss);

    __shared__ float r1[4], r2[4];
    const int wid = tid >> 5, lane = tid & 31;
    if (lane == 0) { r1[wid] = s; r2[wid] = ss; }
    __syncthreads();
    if (tid == 0) {
        float a = 0.0f, c = 0.0f;
        #pragma unroll
        for (int i = 0; i < 4; i++) { a += r1[i]; c += r2[i]; }
        r1[0] = a; r2[0] = c;
    }
    __syncthreads();
    const float mu  = r1[0] * (1.0f / 512.0f);
    const float var = r2[0] * (1.0f / 512.0f) - mu * mu;
    const float rs  = rsqrtf(var + 1e-5f);

    float4 gv = *(const float4*)&g[tid * 4];
    float4 bv = *(const float4*)&b[tid * 4];
    float4 o;
    o.x = (v.x - mu) * rs * gv.x + bv.x;
    o.y = (v.y - mu) * rs * gv.y + bv.y;
    o.z = (v.z - mu) * rs * gv.z + bv.z;
    o.w = (v.w - mu) * rs * gv.w + bv.w;
    *(float4*)&O[base] = o;
}

/* ---------------- launch -------------------------------------------------- */
#define SMEM_G128   71680   /* 2*(128*36 + 32*136)*4 */
#define SMEM_G64    53248   /* 2*( 64*36 + 32*136)*4 */
#define SMEM_ATTN   173120  /* (16*2052 + 1088 + 2*4608 + 128 + 16)*4 */

extern "C" void kernel_launch(void* const* d_in, const int* in_sizes, int n_in,
                              void* d_out, int out_size)
{
    const float* x     = (const float*)d_in[0];
    const float* wq_w  = (const float*)d_in[1];
    const float* wq_b  = (const float*)d_in[2];
    const float* wk_w  = (const float*)d_in[3];
    const float* wk_b  = (const float*)d_in[4];
    const float* wv_w  = (const float*)d_in[5];
    const float* wv_b  = (const float*)d_in[6];
    const float* wo_w  = (const float*)d_in[7];
    const float* wo_b  = (const float*)d_in[8];
    const float* ln1_g = (const float*)d_in[9];
    const float* ln1_b = (const float*)d_in[10];
    const float* fc1_w = (const float*)d_in[11];
    const float* fc1_b = (const float*)d_in[12];
    const float* fc2_w = (const float*)d_in[13];
    const float* fc2_b = (const float*)d_in[14];
    const float* ln2_g = (const float*)d_in[15];
    const float* ln2_b = (const float*)d_in[16];

    float* out = (float*)d_out;

    float *pq, *pk, *pv, *pctx, *ptmp, *ph, *pffn1;
    cudaGetSymbolAddress((void**)&pq,    g_q);
    cudaGetSymbolAddress((void**)&pk,    g_k);
    cudaGetSymbolAddress((void**)&pv,    g_v);
    cudaGetSymbolAddress((void**)&pctx,  g_ctx);
    cudaGetSymbolAddress((void**)&ptmp,  g_tmp);
    cudaGetSymbolAddress((void**)&ph,    g_h);
    cudaGetSymbolAddress((void**)&pffn1, g_ffn1);

    float* attn;
    if ((size_t)out_size >= OUT_ELEMS + ATTN_ELEMS) {
        attn = out + OUT_ELEMS;
    } else {
        cudaGetSymbolAddress((void**)&attn, g_attn_scratch);
    }

    cudaFuncSetAttribute(mma_gemm<64, EPI_QKV>,
                         cudaFuncAttributeMaxDynamicSharedMemorySize, SMEM_G64);
    cudaFuncSetAttribute(mma_gemm<64, EPI_BIAS>,
                         cudaFuncAttributeMaxDynamicSharedMemorySize, SMEM_G64);
    cudaFuncSetAttribute(mma_gemm<128, EPI_RELU>,
                         cudaFuncAttributeMaxDynamicSharedMemorySize, SMEM_G128);
    cudaFuncSetAttribute(attn_fused_kernel,
                         cudaFuncAttributeMaxDynamicSharedMemorySize, SMEM_ATTN);

    /* QKV: one launch (R8 shape: 64x128 tiles, grid 768) */
    mma_gemm<64, EPI_QKV><<<dim3(4, 64, 3), 256, SMEM_G64>>>(
        x, wq_w, wk_w, wv_w, wq_b, wk_b, wv_b, pq, pk, pv,
        BT, D_MODEL, D_MODEL, D_MODEL, D_MODEL, D_MODEL);

    /* fused attention: scores + exp + normalize + attn write + P@V */
    attn_fused_kernel<<<dim3(T_SEQ / 16, BH), 256, SMEM_ATTN>>>(
        pq, pk, pv, attn, pctx);

    /* output projection + LN1 */
    mma_gemm<64, EPI_BIAS><<<dim3(4, 64, 1), 256, SMEM_G64>>>(
        pctx, wo_w, wo_w, wo_w, wo_b, wo_b, wo_b, ptmp, ptmp, ptmp,
        BT, D_MODEL, D_MODEL, D_MODEL, D_MODEL, D_MODEL);
    add_ln_kernel<<<BT, 128>>>(x, ptmp, ln1_g, ln1_b, ph);

    /* FFN + LN2 (R8 shapes: FC1 128x128, FC2 64x128) */
    mma_gemm<128, EPI_RELU><<<dim3(16, 32, 1), 256, SMEM_G128>>>(
        ph, fc1_w, fc1_w, fc1_w, fc1_b, fc1_b, fc1_b, pffn1, pffn1, pffn1,
        BT, D_FF, D_MODEL, D_MODEL, D_FF, D_FF);
    mma_gemm<64, EPI_BIAS><<<dim3(4, 64, 1), 256, SMEM_G64>>>(
        pffn1, fc2_w, fc2_w, fc2_w, fc2_b, fc2_b, fc2_b, ptmp, ptmp, ptmp,
        BT, D_MODEL, D_FF, D_FF, D_MODEL, D_MODEL);
    add_ln_kernel<<<BT, 128>>>(ph, ptmp, ln2_g, ln2_b, out);
}

// round 13
// speedup vs baseline: 1.7799x; 1.3862x over previous
#include <cuda_runtime.h>
#include <math.h>
#include <stdint.h>

#define D_MODEL 512
#define N_HEADS 8
#define D_KK    64
#define D_FF    2048
#define T_SEQ   2048
#define B_BATCH 2
#define BT      (B_BATCH * T_SEQ)
#define BH      (B_BATCH * N_HEADS)

#define OUT_ELEMS  ((size_t)BT * D_MODEL)
#define ATTN_ELEMS ((size_t)BH * T_SEQ * T_SEQ)

#define EPI_BIAS   0
#define EPI_RELU   1
#define EPI_QKV    2

#define LOG2E 1.4426950408889634f

/* ---------------- scratch ------------------------------------------------- */
__device__ float g_q[BH * T_SEQ * D_KK];
__device__ float g_k[BH * T_SEQ * D_KK];
__device__ float g_v[BH * T_SEQ * D_KK];
__device__ float g_ctx[BT * D_MODEL];
__device__ float g_tmp[BT * D_MODEL];
__device__ float g_h[BT * D_MODEL];
__device__ float g_ffn1[BT * D_FF];
__device__ float g_psum[(size_t)BH * T_SEQ * 32];
__device__ float g_attn_scratch[BH * (size_t)T_SEQ * T_SEQ];

/* ---------------- helpers ------------------------------------------------- */
/* tf32 operand: HMMA reads the top bits; raw fp32 bits = RZ-truncated tf32. */
__device__ __forceinline__ uint32_t f2tf(float f) { return __float_as_uint(f); }

__device__ __forceinline__ float ex2(float x) {
    float r;
    asm("ex2.approx.f32 %0, %1;" : "=f"(r) : "f"(x));
    return r;
}
__device__ __forceinline__ void mma8(float c[4], uint32_t a0, uint32_t a1,
                                     uint32_t a2, uint32_t a3,
                                     uint32_t b0, uint32_t b1) {
    asm volatile(
        "mma.sync.aligned.m16n8k8.row.col.f32.tf32.tf32.f32 "
        "{%0,%1,%2,%3}, {%4,%5,%6,%7}, {%8,%9}, {%0,%1,%2,%3};"
        : "+f"(c[0]), "+f"(c[1]), "+f"(c[2]), "+f"(c[3])
        : "r"(a0), "r"(a1), "r"(a2), "r"(a3), "r"(b0), "r"(b1));
}
__device__ __forceinline__ void cp16(float* sdst, const float* gsrc) {
    uint32_t s = (uint32_t)__cvta_generic_to_shared(sdst);
    asm volatile("cp.async.cg.shared.global [%0], [%1], 16;" :: "r"(s), "l"(gsrc));
}
__device__ __forceinline__ float warp_sum(float v) {
    #pragma unroll
    for (int o = 16; o > 0; o >>= 1) v += __shfl_xor_sync(0xffffffffu, v, o);
    return v;
}

/* ---------------- cp.async double-buffered tf32 GEMM (R8 shapes) ---------- */
template <int BM, int EPI>
__global__ __launch_bounds__(256) void mma_gemm(
    const float* __restrict__ A,
    const float* __restrict__ B0, const float* __restrict__ B1, const float* __restrict__ B2,
    const float* __restrict__ bias0, const float* __restrict__ bias1, const float* __restrict__ bias2,
    float* __restrict__ C0, float* __restrict__ C1, float* __restrict__ C2,
    int M, int N, int K, int lda, int ldb, int ldc)
{
    constexpr int KT  = 32;
    constexpr int SA  = KT + 4;                  /* 36  */
    constexpr int SBk = 128 + 8;                 /* 136 */
    constexpr int A_ELE = BM * SA;
    constexpr int B_ELE = KT * SBk;
    constexpr int STG = A_ELE + B_ELE;
    constexpr int AN = (BM == 128) ? 8 : 4;

    extern __shared__ float smem[];

    const int tid = threadIdx.x;
    const int lane = tid & 31, wid = tid >> 5;
    const int z = blockIdx.z;
    const float* B    = (z == 0) ? B0 : (z == 1) ? B1 : B2;
    const float* bias = (z == 0) ? bias0 : (z == 1) ? bias1 : bias2;
    float* C          = (z == 0) ? C0 : (z == 1) ? C1 : C2;

    const int bm = blockIdx.y * BM;
    const int bn = blockIdx.x * 128;
    const int mb = (BM == 128) ? (wid & 3) * 32 : (wid & 1) * 32;
    const int nb = (BM == 128) ? (wid >> 2) * 64 : (wid >> 1) * 32;

    float acc[2][AN][4];
    #pragma unroll
    for (int i = 0; i < 2; i++)
        #pragma unroll
        for (int j = 0; j < AN; j++)
            #pragma unroll
            for (int r = 0; r < 4; r++) acc[i][j][r] = 0.0f;

    auto issue = [&](int k0, int st) {
        float* As = smem + st * STG;
        float* Bs = As + A_ELE;
        #pragma unroll
        for (int i = 0; i < BM * KT / 1024; i++) {
            int f = tid + i * 256;
            int m = f >> 3, k4 = (f & 7) * 4;
            cp16(&As[m * SA + k4], &A[(size_t)(bm + m) * lda + k0 + k4]);
        }
        #pragma unroll
        for (int i = 0; i < 4; i++) {
            int f = tid + i * 256;
            int kk = f >> 5, n4 = (f & 31) * 4;
            cp16(&Bs[kk * SBk + n4], &B[(size_t)(k0 + kk) * ldb + bn + n4]);
        }
        asm volatile("cp.async.commit_group;" ::: "memory");
    };

    issue(0, 0);
    const int nIter = K / KT;
    for (int it = 0; it < nIter; it++) {
        if (it + 1 < nIter) {
            issue((it + 1) * KT, (it + 1) & 1);
            asm volatile("cp.async.wait_group 1;" ::: "memory");
        } else {
            asm volatile("cp.async.wait_group 0;" ::: "memory");
        }
        __syncthreads();

        float* As = smem + (it & 1) * STG;
        float* Bs = As + A_ELE;
        #pragma unroll
        for (int ks = 0; ks < KT / 8; ks++) {
            uint32_t af[2][4], bf[AN][2];
            #pragma unroll
            for (int am = 0; am < 2; am++)
                #pragma unroll
                for (int j = 0; j < 4; j++)
                    af[am][j] = f2tf(As[(mb + am * 16 + (lane >> 2) + (j & 1) * 8) * SA
                                        + ks * 8 + (lane & 3) + (j >> 1) * 4]);
            #pragma unroll
            for (int an = 0; an < AN; an++)
                #pragma unroll
                for (int j = 0; j < 2; j++)
                    bf[an][j] = f2tf(Bs[(ks * 8 + (lane & 3) + j * 4) * SBk
                                        + nb + an * 8 + (lane >> 2)]);
            #pragma unroll
            for (int am = 0; am < 2; am++)
                #pragma unroll
                for (int an = 0; an < AN; an++)
                    mma8(acc[am][an], af[am][0], af[am][1], af[am][2], af[am][3],
                         bf[an][0], bf[an][1]);
        }
        __syncthreads();
    }

    #pragma unroll
    for (int am = 0; am < 2; am++)
        #pragma unroll
        for (int an = 0; an < AN; an++)
            #pragma unroll
            for (int half = 0; half < 2; half++) {
                int m = bm + mb + am * 16 + (lane >> 2) + half * 8;
                int c = bn + nb + an * 8 + (lane & 3) * 2;
                float v0 = acc[am][an][half * 2 + 0] + bias[c];
                float v1 = acc[am][an][half * 2 + 1] + bias[c + 1];
                if (EPI == EPI_RELU) { v0 = fmaxf(v0, 0.0f); v1 = fmaxf(v1, 0.0f); }
                if (EPI == EPI_QKV) {
                    int bb = m >> 11, t = m & (T_SEQ - 1);
                    int h = c >> 6, d = c & (D_KK - 1);
                    *(float2*)&C[((size_t)((bb * N_HEADS + h) * T_SEQ) + t) * D_KK + d]
                        = make_float2(v0, v1);
                } else {
                    *(float2*)&C[(size_t)m * ldc + c] = make_float2(v0, v1);
                }
            }
}

/* ---------------- scores: attn <- exp2(QK^T * sc), partial row sums -------
 * 128 x 128 tile, K=64 one-shot. z = z0 + blockIdx.z (4-head L2 chunk).
 */
__global__ __launch_bounds__(256) void scores_kernel(
    const float* __restrict__ Q, const float* __restrict__ K,
    float* __restrict__ attn, float* __restrict__ psum, int z0)
{
    constexpr int S = 68;
    extern __shared__ float sm[];
    float* Qs = sm;              /* [128][68] */
    float* Ks = sm + 128 * S;    /* [128][68] */

    const int tid = threadIdx.x;
    const int lane = tid & 31, wid = tid >> 5;
    const int z = z0 + blockIdx.z;
    const int bm = blockIdx.y * 128;
    const int bn = blockIdx.x * 128;
    Q += (size_t)z * T_SEQ * D_KK;
    K += (size_t)z * T_SEQ * D_KK;

    #pragma unroll
    for (int i = 0; i < 8; i++) {
        int f = tid + i * 256;
        int m = f >> 4, k4 = (f & 15) * 4;
        cp16(&Qs[m * S + k4], &Q[(size_t)(bm + m) * D_KK + k4]);
        cp16(&Ks[m * S + k4], &K[(size_t)(bn + m) * D_KK + k4]);
    }
    asm volatile("cp.async.commit_group;" ::: "memory");
    asm volatile("cp.async.wait_group 0;" ::: "memory");
    __syncthreads();

    const int mb = (wid & 3) * 32;
    const int nwarp = wid >> 2;
    const int nb = nwarp * 64;

    float acc[2][8][4];
    #pragma unroll
    for (int i = 0; i < 2; i++)
        #pragma unroll
        for (int j = 0; j < 8; j++)
            #pragma unroll
            for (int r = 0; r < 4; r++) acc[i][j][r] = 0.0f;

    #pragma unroll
    for (int ks = 0; ks < 8; ks++) {
        uint32_t af[2][4], bf[8][2];
        #pragma unroll
        for (int am = 0; am < 2; am++)
            #pragma unroll
            for (int j = 0; j < 4; j++)
                af[am][j] = f2tf(Qs[(mb + am * 16 + (lane >> 2) + (j & 1) * 8) * S
                                    + ks * 8 + (lane & 3) + (j >> 1) * 4]);
        #pragma unroll
        for (int an = 0; an < 8; an++)
            #pragma unroll
            for (int j = 0; j < 2; j++)
                bf[an][j] = f2tf(Ks[(nb + an * 8 + (lane >> 2)) * S
                                    + ks * 8 + (lane & 3) + j * 4]);
        #pragma unroll
        for (int am = 0; am < 2; am++)
            #pragma unroll
            for (int an = 0; an < 8; an++)
                mma8(acc[am][an], af[am][0], af[am][1], af[am][2], af[am][3],
                     bf[an][0], bf[an][1]);
    }

    const float sc = 0.125f * LOG2E;
    float* Cz = attn + (size_t)z * T_SEQ * T_SEQ;
    #pragma unroll
    for (int am = 0; am < 2; am++)
        #pragma unroll
        for (int half = 0; half < 2; half++) {
            int m = bm + mb + am * 16 + (lane >> 2) + half * 8;
            float rs = 0.0f;
            #pragma unroll
            for (int an = 0; an < 8; an++) {
                int c = bn + nb + an * 8 + (lane & 3) * 2;
                float e0 = ex2(acc[am][an][half * 2 + 0] * sc);
                float e1 = ex2(acc[am][an][half * 2 + 1] * sc);
                *(float2*)&Cz[(size_t)m * T_SEQ + c] = make_float2(e0, e1);
                rs += e0 + e1;
            }
            rs += __shfl_xor_sync(0xffffffffu, rs, 1);
            rs += __shfl_xor_sync(0xffffffffu, rs, 2);
            if ((lane & 3) == 0)
                psum[((size_t)z * T_SEQ + m) * 32 + blockIdx.x * 2 + nwarp] = rs;
        }
}

/* ---------------- fused psum-reduce + normalize + attn write + P@V --------
 * BM=64 stripe per CTA; KT=64 2-stage. z = z0 + blockIdx.y (L2 chunk).
 */
__global__ __launch_bounds__(256, 3) void attn_pv_kernel(
    float* __restrict__ attn, const float* __restrict__ V,
    const float* __restrict__ psum, float* __restrict__ ctx, int z0)
{
    constexpr int KT = 64;
    constexpr int BM = 64;
    constexpr int SA = 68;     /* [m=64][k=64]+4 */
    constexpr int SV = 72;     /* [k=64][n=64]+8 */
    constexpr int A_ELE = BM * SA;             /* 4352 */
    constexpr int STG = A_ELE + KT * SV;       /* 8960 */
    extern __shared__ float sm[];
    float* invs = sm + 2 * STG;

    const int tid = threadIdx.x;
    const int lane = tid & 31, wid = tid >> 5;
    const int bm = blockIdx.x * BM;
    const int z = z0 + blockIdx.y;
    attn += (size_t)z * T_SEQ * T_SEQ;
    V    += (size_t)z * T_SEQ * D_KK;

    auto issue = [&](int k0, int st) {
        float* As = sm + st * STG;
        float* Vs = As + A_ELE;
        #pragma unroll
        for (int i = 0; i < 4; i++) {
            int f = tid + i * 256;
            int m = f >> 4, k4 = (f & 15) * 4;
            cp16(&As[m * SA + k4], &attn[(size_t)(bm + m) * T_SEQ + k0 + k4]);
        }
        #pragma unroll
        for (int i = 0; i < 4; i++) {
            int f = tid + i * 256;
            int kk = f >> 4, c4 = (f & 15) * 4;
            cp16(&Vs[kk * SV + c4], &V[(size_t)(k0 + kk) * D_KK + c4]);
        }
        asm volatile("cp.async.commit_group;" ::: "memory");
    };

    issue(0, 0);

    /* reduce this stripe's psums -> invs (CTA exclusively owns rows) */
    if (tid < BM) {
        const float4* p = (const float4*)(psum + ((size_t)z * T_SEQ + bm + tid) * 32);
        float s = 0.0f;
        #pragma unroll
        for (int i = 0; i < 8; i++) {
            float4 v = p[i];
            s += v.x + v.y + v.z + v.w;
        }
        invs[tid] = 1.0f / s;
    }
    __syncthreads();

    const int mb = (wid & 1) * 32;
    const int nb = (wid >> 1) * 16;

    float acc[2][2][4];
    #pragma unroll
    for (int i = 0; i < 2; i++)
        #pragma unroll
        for (int j = 0; j < 2; j++)
            #pragma unroll
            for (int r = 0; r < 4; r++) acc[i][j][r] = 0.0f;

    const int nIter = T_SEQ / KT;   /* 32 */
    for (int it = 0; it < nIter; it++) {
        if (it + 1 < nIter) {
            issue((it + 1) * KT, (it + 1) & 1);
            asm volatile("cp.async.wait_group 1;" ::: "memory");
        } else {
            asm volatile("cp.async.wait_group 0;" ::: "memory");
        }
        __syncthreads();

        float* As = sm + (it & 1) * STG;
        float* Vs = As + A_ELE;

        #pragma unroll
        for (int ks = 0; ks < KT / 8; ks++) {
            uint32_t af[2][4], bf[2][2];
            #pragma unroll
            for (int am = 0; am < 2; am++)
                #pragma unroll
                for (int j = 0; j < 4; j++)
                    af[am][j] = f2tf(As[(mb + am * 16 + (lane >> 2) + (j & 1) * 8) * SA
                                        + ks * 8 + (lane & 3) + (j >> 1) * 4]);
            #pragma unroll
            for (int an = 0; an < 2; an++)
                #pragma unroll
                for (int j = 0; j < 2; j++)
                    bf[an][j] = f2tf(Vs[(ks * 8 + (lane & 3) + j * 4) * SV
                                        + nb + an * 8 + (lane >> 2)]);
            #pragma unroll
            for (int am = 0; am < 2; am++)
                #pragma unroll
                for (int an = 0; an < 2; an++)
                    mma8(acc[am][an], af[am][0], af[am][1], af[am][2], af[am][3],
                         bf[an][0], bf[an][1]);
        }

        /* normalized in-place attn write from smem (coalesced STG.128) */
        #pragma unroll
        for (int i = 0; i < 4; i++) {
            int f = tid + i * 256;
            int m = f >> 4, k4 = (f & 15) * 4;
            float4 v = *(const float4*)&As[m * SA + k4];
            float iv = invs[m];
            v.x *= iv; v.y *= iv; v.z *= iv; v.w *= iv;
            *(float4*)&attn[(size_t)(bm + m) * T_SEQ + it * KT + k4] = v;
        }
        __syncthreads();
    }

    const int b = z >> 3, h = z & 7;
    float* Cz = ctx + (size_t)b * T_SEQ * D_MODEL + h * D_KK;
    #pragma unroll
    for (int am = 0; am < 2; am++)
        #pragma unroll
        for (int an = 0; an < 2; an++)
            #pragma unroll
            for (int half = 0; half < 2; half++) {
                int mr = mb + am * 16 + (lane >> 2) + half * 8;
                int c = nb + an * 8 + (lane & 3) * 2;
                float iv = invs[mr];
                *(float2*)&Cz[(size_t)(bm + mr) * D_MODEL + c]
                    = make_float2(acc[am][an][half * 2 + 0] * iv,
                                  acc[am][an][half * 2 + 1] * iv);
            }
}

/* ---------------- fused residual add + LayerNorm ------------------------- */
__global__ __launch_bounds__(128) void add_ln_kernel(
    const float* __restrict__ X, const float* __restrict__ Y,
    const float* __restrict__ g, const float* __restrict__ b,
    float* __restrict__ O)
{
    const int tid = threadIdx.x;
    const size_t base = (size_t)blockIdx.x * D_MODEL + tid * 4;
    float4 xv = *(const float4*)&X[base];
    float4 yv = *(const float4*)&Y[base];
    float4 v = make_float4(xv.x + yv.x, xv.y + yv.y, xv.z + yv.z, xv.w + yv.w);

    float s  = v.x + v.y + v.z + v.w;
    float ss = v.x * v.x + v.y * v.y + v.z * v.z + v.w * v.w;
    s = warp_sum(s);
    ss = warp_sum(ss);

    __shared__ float r1[4], r2[4];
    const int wid = tid >> 5, lane = tid & 31;
    if (lane == 0) { r1[wid] = s; r2[wid] = ss; }
    __syncthreads();
    if (tid == 0) {
        float a = 0.0f, c = 0.0f;
        #pragma unroll
        for (int i = 0; i < 4; i++) { a += r1[i]; c += r2[i]; }
        r1[0] = a; r2[0] = c;
    }
    __syncthreads();
    const float mu  = r1[0] * (1.0f / 512.0f);
    const float var = r2[0] * (1.0f / 512.0f) - mu * mu;
    const float rs  = rsqrtf(var + 1e-5f);

    float4 gv = *(const float4*)&g[tid * 4];
    float4 bv = *(const float4*)&b[tid * 4];
    float4 o;
    o.x = (v.x - mu) * rs * gv.x + bv.x;
    o.y = (v.y - mu) * rs * gv.y + bv.y;
    o.z = (v.z - mu) * rs * gv.z + bv.z;
    o.w = (v.w - mu) * rs * gv.w + bv.w;
    *(float4*)&O[base] = o;
}

/* ---------------- launch -------------------------------------------------- */
#define SMEM_G128   71680   /* 2*(128*36 + 32*136)*4 */
#define SMEM_G64    53248   /* 2*( 64*36 + 32*136)*4 */
#define SMEM_SCORES 69632   /* 2*128*68*4 */
#define SMEM_PV     71936   /* (2*8960 + 64)*4 */
#define ZCHUNK      4       /* 4 heads: 67MB expS, fits 126MB L2 */

extern "C" void kernel_launch(void* const* d_in, const int* in_sizes, int n_in,
                              void* d_out, int out_size)
{
    const float* x     = (const float*)d_in[0];
    const float* wq_w  = (const float*)d_in[1];
    const float* wq_b  = (const float*)d_in[2];
    const float* wk_w  = (const float*)d_in[3];
    const float* wk_b  = (const float*)d_in[4];
    const float* wv_w  = (const float*)d_in[5];
    const float* wv_b  = (const float*)d_in[6];
    const float* wo_w  = (const float*)d_in[7];
    const float* wo_b  = (const float*)d_in[8];
    const float* ln1_g = (const float*)d_in[9];
    const float* ln1_b = (const float*)d_in[10];
    const float* fc1_w = (const float*)d_in[11];
    const float* fc1_b = (const float*)d_in[12];
    const float* fc2_w = (const float*)d_in[13];
    const float* fc2_b = (const float*)d_in[14];
    const float* ln2_g = (const float*)d_in[15];
    const float* ln2_b = (const float*)d_in[16];

    float* out = (float*)d_out;

    float *pq, *pk, *pv, *pctx, *ptmp, *ph, *pffn1, *ppsum;
    cudaGetSymbolAddress((void**)&pq,    g_q);
    cudaGetSymbolAddress((void**)&pk,    g_k);
    cudaGetSymbolAddress((void**)&pv,    g_v);
    cudaGetSymbolAddress((void**)&pctx,  g_ctx);
    cudaGetSymbolAddress((void**)&ptmp,  g_tmp);
    cudaGetSymbolAddress((void**)&ph,    g_h);
    cudaGetSymbolAddress((void**)&pffn1, g_ffn1);
    cudaGetSymbolAddress((void**)&ppsum, g_psum);

    float* attn;
    if ((size_t)out_size >= OUT_ELEMS + ATTN_ELEMS) {
        attn = out + OUT_ELEMS;
    } else {
        cudaGetSymbolAddress((void**)&attn, g_attn_scratch);
    }

    cudaFuncSetAttribute(mma_gemm<64, EPI_QKV>,
                         cudaFuncAttributeMaxDynamicSharedMemorySize, SMEM_G64);
    cudaFuncSetAttribute(mma_gemm<64, EPI_BIAS>,
                         cudaFuncAttributeMaxDynamicSharedMemorySize, SMEM_G64);
    cudaFuncSetAttribute(mma_gemm<128, EPI_RELU>,
                         cudaFuncAttributeMaxDynamicSharedMemorySize, SMEM_G128);
    cudaFuncSetAttribute(scores_kernel,
                         cudaFuncAttributeMaxDynamicSharedMemorySize, SMEM_SCORES);
    cudaFuncSetAttribute(attn_pv_kernel,
                         cudaFuncAttributeMaxDynamicSharedMemorySize, SMEM_PV);

    /* QKV: one launch (64x128 tiles, grid 768) */
    mma_gemm<64, EPI_QKV><<<dim3(4, 64, 3), 256, SMEM_G64>>>(
        x, wq_w, wk_w, wv_w, wq_b, wk_b, wv_b, pq, pk, pv,
        BT, D_MODEL, D_MODEL, D_MODEL, D_MODEL, D_MODEL);

    /* attention in 4-head L2 chunks: scores(chunk) then PV(chunk) so the
     * 67MB expS chunk is still L2-resident when PV reads it. */
    for (int z0 = 0; z0 < BH; z0 += ZCHUNK) {
        scores_kernel<<<dim3(16, 16, ZCHUNK), 256, SMEM_SCORES>>>(
            pq, pk, attn, ppsum, z0);
        attn_pv_kernel<<<dim3(T_SEQ / 64, ZCHUNK), 256, SMEM_PV>>>(
            attn, pv, ppsum, pctx, z0);
    }

    /* output projection + LN1 */
    mma_gemm<64, EPI_BIAS><<<dim3(4, 64, 1), 256, SMEM_G64>>>(
        pctx, wo_w, wo_w, wo_w, wo_b, wo_b, wo_b, ptmp, ptmp, ptmp,
        BT, D_MODEL, D_MODEL, D_MODEL, D_MODEL, D_MODEL);
    add_ln_kernel<<<BT, 128>>>(x, ptmp, ln1_g, ln1_b, ph);

    /* FFN + LN2 (FC1 128x128, FC2 64x128) */
    mma_gemm<128, EPI_RELU><<<dim3(16, 32, 1), 256, SMEM_G128>>>(
        ph, fc1_w, fc1_w, fc1_w, fc1_b, fc1_b, fc1_b, pffn1, pffn1, pffn1,
        BT, D_FF, D_MODEL, D_MODEL, D_FF, D_FF);
    mma_gemm<64, EPI_BIAS><<<dim3(4, 64, 1), 256, SMEM_G64>>>(
        pffn1, fc2_w, fc2_w, fc2_w, fc2_b, fc2_b, fc2_b, ptmp, ptmp, ptmp,
        BT, D_MODEL, D_FF, D_FF, D_MODEL, D_MODEL);
    add_ln_kernel<<<BT, 128>>>(ph, ptmp, ln2_g, ln2_b, out);
}

// round 14
// speedup vs baseline: 1.8476x; 1.0381x over previous
#include <cuda_runtime.h>
#include <cuda_fp16.h>
#include <math.h>
#include <stdint.h>

#define D_MODEL 512
#define N_HEADS 8
#define D_KK    64
#define D_FF    2048
#define T_SEQ   2048
#define B_BATCH 2
#define BT      (B_BATCH * T_SEQ)
#define BH      (B_BATCH * N_HEADS)

#define OUT_ELEMS  ((size_t)BT * D_MODEL)
#define ATTN_ELEMS ((size_t)BH * T_SEQ * T_SEQ)

#define EPI_BIAS   0
#define EPI_RELU   1
#define EPI_QKV    2

#define LOG2E 1.4426950408889634f

/* ---------------- scratch ------------------------------------------------- */
__device__ float  g_q[BH * T_SEQ * D_KK];
__device__ float  g_k[BH * T_SEQ * D_KK];
__device__ float  g_v[BH * T_SEQ * D_KK];
__device__ float  g_ctx[BT * D_MODEL];
__device__ float  g_tmp[BT * D_MODEL];
__device__ float  g_h[BT * D_MODEL];
__device__ float  g_ffn1[BT * D_FF];
__device__ float  g_psum[(size_t)BH * T_SEQ * 32];
__device__ __half g_expS[(size_t)BH * T_SEQ * T_SEQ];   /* fp16 intermediate */
__device__ float  g_attn_scratch[BH * (size_t)T_SEQ * T_SEQ];

/* ---------------- helpers ------------------------------------------------- */
/* RZ path (fast, mainloop of dense GEMMs + PV): raw fp32 bits. */
__device__ __forceinline__ uint32_t f2tf(float f) { return __float_as_uint(f); }
/* RN path (scores QK^T only): proper round-to-nearest tf32. */
__device__ __forceinline__ uint32_t f2tfr(float f) {
    uint32_t r;
    asm("cvt.rna.tf32.f32 %0, %1;" : "=r"(r) : "f"(f));
    return r;
}
__device__ __forceinline__ float ex2(float x) {
    float r;
    asm("ex2.approx.f32 %0, %1;" : "=f"(r) : "f"(x));
    return r;
}
__device__ __forceinline__ void mma8(float c[4], uint32_t a0, uint32_t a1,
                                     uint32_t a2, uint32_t a3,
                                     uint32_t b0, uint32_t b1) {
    asm volatile(
        "mma.sync.aligned.m16n8k8.row.col.f32.tf32.tf32.f32 "
        "{%0,%1,%2,%3}, {%4,%5,%6,%7}, {%8,%9}, {%0,%1,%2,%3};"
        : "+f"(c[0]), "+f"(c[1]), "+f"(c[2]), "+f"(c[3])
        : "r"(a0), "r"(a1), "r"(a2), "r"(a3), "r"(b0), "r"(b1));
}
__device__ __forceinline__ void cp16(void* sdst, const void* gsrc) {
    uint32_t s = (uint32_t)__cvta_generic_to_shared(sdst);
    asm volatile("cp.async.cg.shared.global [%0], [%1], 16;" :: "r"(s), "l"(gsrc));
}
__device__ __forceinline__ float warp_sum(float v) {
    #pragma unroll
    for (int o = 16; o > 0; o >>= 1) v += __shfl_xor_sync(0xffffffffu, v, o);
    return v;
}

/* ---------------- cp.async double-buffered tf32 GEMM (R8 shapes) ---------- */
template <int BM, int EPI>
__global__ __launch_bounds__(256) void mma_gemm(
    const float* __restrict__ A,
    const float* __restrict__ B0, const float* __restrict__ B1, const float* __restrict__ B2,
    const float* __restrict__ bias0, const float* __restrict__ bias1, const float* __restrict__ bias2,
    float* __restrict__ C0, float* __restrict__ C1, float* __restrict__ C2,
    int M, int N, int K, int lda, int ldb, int ldc)
{
    constexpr int KT  = 32;
    constexpr int SA  = KT + 4;                  /* 36  */
    constexpr int SBk = 128 + 8;                 /* 136 */
    constexpr int A_ELE = BM * SA;
    constexpr int B_ELE = KT * SBk;
    constexpr int STG = A_ELE + B_ELE;
    constexpr int AN = (BM == 128) ? 8 : 4;

    extern __shared__ float smem[];

    const int tid = threadIdx.x;
    const int lane = tid & 31, wid = tid >> 5;
    const int z = blockIdx.z;
    const float* B    = (z == 0) ? B0 : (z == 1) ? B1 : B2;
    const float* bias = (z == 0) ? bias0 : (z == 1) ? bias1 : bias2;
    float* C          = (z == 0) ? C0 : (z == 1) ? C1 : C2;

    const int bm = blockIdx.y * BM;
    const int bn = blockIdx.x * 128;
    const int mb = (BM == 128) ? (wid & 3) * 32 : (wid & 1) * 32;
    const int nb = (BM == 128) ? (wid >> 2) * 64 : (wid >> 1) * 32;

    float acc[2][AN][4];
    #pragma unroll
    for (int i = 0; i < 2; i++)
        #pragma unroll
        for (int j = 0; j < AN; j++)
            #pragma unroll
            for (int r = 0; r < 4; r++) acc[i][j][r] = 0.0f;

    auto issue = [&](int k0, int st) {
        float* As = smem + st * STG;
        float* Bs = As + A_ELE;
        #pragma unroll
        for (int i = 0; i < BM * KT / 1024; i++) {
            int f = tid + i * 256;
            int m = f >> 3, k4 = (f & 7) * 4;
            cp16(&As[m * SA + k4], &A[(size_t)(bm + m) * lda + k0 + k4]);
        }
        #pragma unroll
        for (int i = 0; i < 4; i++) {
            int f = tid + i * 256;
            int kk = f >> 5, n4 = (f & 31) * 4;
            cp16(&Bs[kk * SBk + n4], &B[(size_t)(k0 + kk) * ldb + bn + n4]);
        }
        asm volatile("cp.async.commit_group;" ::: "memory");
    };

    issue(0, 0);
    const int nIter = K / KT;
    for (int it = 0; it < nIter; it++) {
        if (it + 1 < nIter) {
            issue((it + 1) * KT, (it + 1) & 1);
            asm volatile("cp.async.wait_group 1;" ::: "memory");
        } else {
            asm volatile("cp.async.wait_group 0;" ::: "memory");
        }
        __syncthreads();

        float* As = smem + (it & 1) * STG;
        float* Bs = As + A_ELE;
        #pragma unroll
        for (int ks = 0; ks < KT / 8; ks++) {
            uint32_t af[2][4], bf[AN][2];
            #pragma unroll
            for (int am = 0; am < 2; am++)
                #pragma unroll
                for (int j = 0; j < 4; j++)
                    af[am][j] = f2tf(As[(mb + am * 16 + (lane >> 2) + (j & 1) * 8) * SA
                                        + ks * 8 + (lane & 3) + (j >> 1) * 4]);
            #pragma unroll
            for (int an = 0; an < AN; an++)
                #pragma unroll
                for (int j = 0; j < 2; j++)
                    bf[an][j] = f2tf(Bs[(ks * 8 + (lane & 3) + j * 4) * SBk
                                        + nb + an * 8 + (lane >> 2)]);
            #pragma unroll
            for (int am = 0; am < 2; am++)
                #pragma unroll
                for (int an = 0; an < AN; an++)
                    mma8(acc[am][an], af[am][0], af[am][1], af[am][2], af[am][3],
                         bf[an][0], bf[an][1]);
        }
        __syncthreads();
    }

    #pragma unroll
    for (int am = 0; am < 2; am++)
        #pragma unroll
        for (int an = 0; an < AN; an++)
            #pragma unroll
            for (int half = 0; half < 2; half++) {
                int m = bm + mb + am * 16 + (lane >> 2) + half * 8;
                int c = bn + nb + an * 8 + (lane & 3) * 2;
                float v0 = acc[am][an][half * 2 + 0] + bias[c];
                float v1 = acc[am][an][half * 2 + 1] + bias[c + 1];
                if (EPI == EPI_RELU) { v0 = fmaxf(v0, 0.0f); v1 = fmaxf(v1, 0.0f); }
                if (EPI == EPI_QKV) {
                    int bb = m >> 11, t = m & (T_SEQ - 1);
                    int h = c >> 6, d = c & (D_KK - 1);
                    *(float2*)&C[((size_t)((bb * N_HEADS + h) * T_SEQ) + t) * D_KK + d]
                        = make_float2(v0, v1);
                } else {
                    *(float2*)&C[(size_t)m * ldc + c] = make_float2(v0, v1);
                }
            }
}

/* ---------------- scores: expS(fp16) <- exp2(QK^T * sc), partial sums -----
 * 128 x 128 tile, K=64 one-shot. RN tf32 fragments (accuracy headroom for
 * the fp16 quantization). Row sums computed over the QUANTIZED values.
 */
__global__ __launch_bounds__(256) void scores_kernel(
    const float* __restrict__ Q, const float* __restrict__ K,
    __half* __restrict__ expS, float* __restrict__ psum)
{
    constexpr int S = 68;
    extern __shared__ float sm[];
    float* Qs = sm;              /* [128][68] */
    float* Ks = sm + 128 * S;    /* [128][68] */

    const int tid = threadIdx.x;
    const int lane = tid & 31, wid = tid >> 5;
    const int z = blockIdx.z;
    const int bm = blockIdx.y * 128;
    const int bn = blockIdx.x * 128;
    Q += (size_t)z * T_SEQ * D_KK;
    K += (size_t)z * T_SEQ * D_KK;

    #pragma unroll
    for (int i = 0; i < 8; i++) {
        int f = tid + i * 256;
        int m = f >> 4, k4 = (f & 15) * 4;
        cp16(&Qs[m * S + k4], &Q[(size_t)(bm + m) * D_KK + k4]);
        cp16(&Ks[m * S + k4], &K[(size_t)(bn + m) * D_KK + k4]);
    }
    asm volatile("cp.async.commit_group;" ::: "memory");
    asm volatile("cp.async.wait_group 0;" ::: "memory");
    __syncthreads();

    const int mb = (wid & 3) * 32;
    const int nwarp = wid >> 2;
    const int nb = nwarp * 64;

    float acc[2][8][4];
    #pragma unroll
    for (int i = 0; i < 2; i++)
        #pragma unroll
        for (int j = 0; j < 8; j++)
            #pragma unroll
            for (int r = 0; r < 4; r++) acc[i][j][r] = 0.0f;

    #pragma unroll
    for (int ks = 0; ks < 8; ks++) {
        uint32_t af[2][4], bf[8][2];
        #pragma unroll
        for (int am = 0; am < 2; am++)
            #pragma unroll
            for (int j = 0; j < 4; j++)
                af[am][j] = f2tfr(Qs[(mb + am * 16 + (lane >> 2) + (j & 1) * 8) * S
                                     + ks * 8 + (lane & 3) + (j >> 1) * 4]);
        #pragma unroll
        for (int an = 0; an < 8; an++)
            #pragma unroll
            for (int j = 0; j < 2; j++)
                bf[an][j] = f2tfr(Ks[(nb + an * 8 + (lane >> 2)) * S
                                     + ks * 8 + (lane & 3) + j * 4]);
        #pragma unroll
        for (int am = 0; am < 2; am++)
            #pragma unroll
            for (int an = 0; an < 8; an++)
                mma8(acc[am][an], af[am][0], af[am][1], af[am][2], af[am][3],
                     bf[an][0], bf[an][1]);
    }

    const float sc = 0.125f * LOG2E;
    __half* Ez = expS + (size_t)z * T_SEQ * T_SEQ;
    #pragma unroll
    for (int am = 0; am < 2; am++)
        #pragma unroll
        for (int half = 0; half < 2; half++) {
            int m = bm + mb + am * 16 + (lane >> 2) + half * 8;
            float rs = 0.0f;
            #pragma unroll
            for (int an = 0; an < 8; an++) {
                int c = bn + nb + an * 8 + (lane & 3) * 2;
                float e0 = ex2(acc[am][an][half * 2 + 0] * sc);
                float e1 = ex2(acc[am][an][half * 2 + 1] * sc);
                __half2 hv = __floats2half2_rn(e0, e1);
                *(__half2*)&Ez[(size_t)m * T_SEQ + c] = hv;
                float2 qv = __half22float2(hv);   /* sum the quantized values */
                rs += qv.x + qv.y;
            }
            rs += __shfl_xor_sync(0xffffffffu, rs, 1);
            rs += __shfl_xor_sync(0xffffffffu, rs, 2);
            if ((lane & 3) == 0)
                psum[((size_t)z * T_SEQ + m) * 32 + blockIdx.x * 2 + nwarp] = rs;
        }
}

/* ---------------- fused psum-reduce + normalize + attn write + P@V --------
 * BM=64 stripe per CTA; KT=64 2-stage. P read as fp16, converted to fp32
 * smem once per tile; rest identical to the measured-best R8 kernel.
 */
__global__ __launch_bounds__(256, 3) void attn_pv_kernel(
    const __half* __restrict__ expS, const float* __restrict__ V,
    const float* __restrict__ psum, float* __restrict__ attn,
    float* __restrict__ ctx)
{
    constexpr int KT = 64;
    constexpr int BM = 64;
    constexpr int SA = 68;                        /* fp32 As stride */
    constexpr int SV = 72;
    constexpr int AS_ELE = BM * SA;               /* 4352 fl */
    constexpr int VS_ELE = KT * SV;               /* 4608 fl, x2 stages */
    constexpr int AH_ELE = BM * KT / 2;           /* 2048 fl (half tile), x2 */
    extern __shared__ float sm[];
    float* As   = sm;                              /* single buffer */
    float* Vs0  = As + AS_ELE;
    float* Ah0  = Vs0 + 2 * VS_ELE;
    float* invs = Ah0 + 2 * AH_ELE;

    const int tid = threadIdx.x;
    const int lane = tid & 31, wid = tid >> 5;
    const int bm = blockIdx.x * BM;
    const int z = blockIdx.y;
    expS += (size_t)z * T_SEQ * T_SEQ;
    V    += (size_t)z * T_SEQ * D_KK;
    attn += (size_t)z * T_SEQ * T_SEQ;

    auto issue = [&](int k0, int st) {
        __half* Ah = (__half*)(Ah0 + st * AH_ELE);
        float*  Vs = Vs0 + st * VS_ELE;
        #pragma unroll
        for (int i = 0; i < 2; i++) {              /* 64x64 halfs = 512 x 16B */
            int f = tid + i * 256;
            int m = f >> 3, k8 = (f & 7) * 8;
            cp16(&Ah[m * KT + k8], &expS[(size_t)(bm + m) * T_SEQ + k0 + k8]);
        }
        #pragma unroll
        for (int i = 0; i < 4; i++) {
            int f = tid + i * 256;
            int kk = f >> 4, c4 = (f & 15) * 4;
            cp16(&Vs[kk * SV + c4], &V[(size_t)(k0 + kk) * D_KK + c4]);
        }
        asm volatile("cp.async.commit_group;" ::: "memory");
    };

    issue(0, 0);

    /* reduce this stripe's psums -> invs (CTA exclusively owns rows) */
    if (tid < BM) {
        const float4* p = (const float4*)(psum + ((size_t)z * T_SEQ + bm + tid) * 32);
        float s = 0.0f;
        #pragma unroll
        for (int i = 0; i < 8; i++) {
            float4 v = p[i];
            s += v.x + v.y + v.z + v.w;
        }
        invs[tid] = 1.0f / s;
    }
    __syncthreads();

    const int mb = (wid & 1) * 32;
    const int nb = (wid >> 1) * 16;

    float acc[2][2][4];
    #pragma unroll
    for (int i = 0; i < 2; i++)
        #pragma unroll
        for (int j = 0; j < 2; j++)
            #pragma unroll
            for (int r = 0; r < 4; r++) acc[i][j][r] = 0.0f;

    const int nIter = T_SEQ / KT;   /* 32 */
    for (int it = 0; it < nIter; it++) {
        if (it + 1 < nIter) {
            issue((it + 1) * KT, (it + 1) & 1);
            asm volatile("cp.async.wait_group 1;" ::: "memory");
        } else {
            asm volatile("cp.async.wait_group 0;" ::: "memory");
        }
        __syncthreads();

        /* convert the fp16 P tile to fp32 As (single buffer) */
        {
            const uint32_t* Ah = (const uint32_t*)(Ah0 + (it & 1) * AH_ELE);
            #pragma unroll
            for (int i = 0; i < 8; i++) {          /* 2048 half2 / 256 thr */
                int idx2 = tid + i * 256;
                int m = idx2 >> 5, c2 = (idx2 & 31) * 2;
                __half2 hv = *(const __half2*)&Ah[idx2];
                float2 fv = __half22float2(hv);
                *(float2*)&As[m * SA + c2] = fv;
                (void)m; (void)c2;
            }
        }
        __syncthreads();

        float* Vs = Vs0 + (it & 1) * VS_ELE;

        #pragma unroll
        for (int ks = 0; ks < KT / 8; ks++) {
            uint32_t af[2][4], bf[2][2];
            #pragma unroll
            for (int am = 0; am < 2; am++)
                #pragma unroll
                for (int j = 0; j < 4; j++)
                    af[am][j] = f2tf(As[(mb + am * 16 + (lane >> 2) + (j & 1) * 8) * SA
                                        + ks * 8 + (lane & 3) + (j >> 1) * 4]);
            #pragma unroll
            for (int an = 0; an < 2; an++)
                #pragma unroll
                for (int j = 0; j < 2; j++)
                    bf[an][j] = f2tf(Vs[(ks * 8 + (lane & 3) + j * 4) * SV
                                        + nb + an * 8 + (lane >> 2)]);
            #pragma unroll
            for (int am = 0; am < 2; am++)
                #pragma unroll
                for (int an = 0; an < 2; an++)
                    mma8(acc[am][an], af[am][0], af[am][1], af[am][2], af[am][3],
                         bf[an][0], bf[an][1]);
        }

        /* normalized attn write from As (coalesced STG.128) */
        #pragma unroll
        for (int i = 0; i < 4; i++) {
            int f = tid + i * 256;
            int m = f >> 4, k4 = (f & 15) * 4;
            float4 v = *(const float4*)&As[m * SA + k4];
            float iv = invs[m];
            v.x *= iv; v.y *= iv; v.z *= iv; v.w *= iv;
            *(float4*)&attn[(size_t)(bm + m) * T_SEQ + it * KT + k4] = v;
        }
        __syncthreads();
    }

    const int b = z >> 3, h = z & 7;
    float* Cz = ctx + (size_t)b * T_SEQ * D_MODEL + h * D_KK;
    #pragma unroll
    for (int am = 0; am < 2; am++)
        #pragma unroll
        for (int an = 0; an < 2; an++)
            #pragma unroll
            for (int half = 0; half < 2; half++) {
                int mr = mb + am * 16 + (lane >> 2) + half * 8;
                int c = nb + an * 8 + (lane & 3) * 2;
                float iv = invs[mr];
                *(float2*)&Cz[(size_t)(bm + mr) * D_MODEL + c]
                    = make_float2(acc[am][an][half * 2 + 0] * iv,
                                  acc[am][an][half * 2 + 1] * iv);
            }
}

/* ---------------- fused residual add + LayerNorm ------------------------- */
__global__ __launch_bounds__(128) void add_ln_kernel(
    const float* __restrict__ X, const float* __restrict__ Y,
    const float* __restrict__ g, const float* __restrict__ b,
    float* __restrict__ O)
{
    const int tid = threadIdx.x;
    const size_t base = (size_t)blockIdx.x * D_MODEL + tid * 4;
    float4 xv = *(const float4*)&X[base];
    float4 yv = *(const float4*)&Y[base];
    float4 v = make_float4(xv.x + yv.x, xv.y + yv.y, xv.z + yv.z, xv.w + yv.w);

    float s  = v.x + v.y + v.z + v.w;
    float ss = v.x * v.x + v.y * v.y + v.z * v.z + v.w * v.w;
    s = warp_sum(s);
    ss = warp_sum(ss);

    __shared__ float r1[4], r2[4];
    const int wid = tid >> 5, lane = tid & 31;
    if (lane == 0) { r1[wid] = s; r2[wid] = ss; }
    __syncthreads();
    if (tid == 0) {
        float a = 0.0f, c = 0.0f;
        #pragma unroll
        for (int i = 0; i < 4; i++) { a += r1[i]; c += r2[i]; }
        r1[0] = a; r2[0] = c;
    }
    __syncthreads();
    const float mu  = r1[0] * (1.0f / 512.0f);
    const float var = r2[0] * (1.0f / 512.0f) - mu * mu;
    const float rs  = rsqrtf(var + 1e-5f);

    float4 gv = *(const float4*)&g[tid * 4];
    float4 bv = *(const float4*)&b[tid * 4];
    float4 o;
    o.x = (v.x - mu) * rs * gv.x + bv.x;
    o.y = (v.y - mu) * rs * gv.y + bv.y;
    o.z = (v.z - mu) * rs * gv.z + bv.z;
    o.w = (v.w - mu) * rs * gv.w + bv.w;
    *(float4*)&O[base] = o;
}

/* ---------------- launch -------------------------------------------------- */
#define SMEM_G128   71680   /* 2*(128*36 + 32*136)*4 */
#define SMEM_G64    53248   /* 2*( 64*36 + 32*136)*4 */
#define SMEM_SCORES 69632   /* 2*128*68*4 */
#define SMEM_PV     70912   /* (4352 + 2*4608 + 2*2048 + 64)*4 */

extern "C" void kernel_launch(void* const* d_in, const int* in_sizes, int n_in,
                              void* d_out, int out_size)
{
    const float* x     = (const float*)d_in[0];
    const float* wq_w  = (const float*)d_in[1];
    const float* wq_b  = (const float*)d_in[2];
    const float* wk_w  = (const float*)d_in[3];
    const float* wk_b  = (const float*)d_in[4];
    const float* wv_w  = (const float*)d_in[5];
    const float* wv_b  = (const float*)d_in[6];
    const float* wo_w  = (const float*)d_in[7];
    const float* wo_b  = (const float*)d_in[8];
    const float* ln1_g = (const float*)d_in[9];
    const float* ln1_b = (const float*)d_in[10];
    const float* fc1_w = (const float*)d_in[11];
    const float* fc1_b = (const float*)d_in[12];
    const float* fc2_w = (const float*)d_in[13];
    const float* fc2_b = (const float*)d_in[14];
    const float* ln2_g = (const float*)d_in[15];
    const float* ln2_b = (const float*)d_in[16];

    float* out = (float*)d_out;

    float *pq, *pk, *pv, *pctx, *ptmp, *ph, *pffn1, *ppsum;
    __half* pexp;
    cudaGetSymbolAddress((void**)&pq,    g_q);
    cudaGetSymbolAddress((void**)&pk,    g_k);
    cudaGetSymbolAddress((void**)&pv,    g_v);
    cudaGetSymbolAddress((void**)&pctx,  g_ctx);
    cudaGetSymbolAddress((void**)&ptmp,  g_tmp);
    cudaGetSymbolAddress((void**)&ph,    g_h);
    cudaGetSymbolAddress((void**)&pffn1, g_ffn1);
    cudaGetSymbolAddress((void**)&ppsum, g_psum);
    cudaGetSymbolAddress((void**)&pexp,  g_expS);

    float* attn;
    if ((size_t)out_size >= OUT_ELEMS + ATTN_ELEMS) {
        attn = out + OUT_ELEMS;
    } else {
        cudaGetSymbolAddress((void**)&attn, g_attn_scratch);
    }

    cudaFuncSetAttribute(mma_gemm<64, EPI_QKV>,
                         cudaFuncAttributeMaxDynamicSharedMemorySize, SMEM_G64);
    cudaFuncSetAttribute(mma_gemm<64, EPI_BIAS>,
                         cudaFuncAttributeMaxDynamicSharedMemorySize, SMEM_G64);
    cudaFuncSetAttribute(mma_gemm<128, EPI_RELU>,
                         cudaFuncAttributeMaxDynamicSharedMemorySize, SMEM_G128);
    cudaFuncSetAttribute(scores_kernel,
                         cudaFuncAttributeMaxDynamicSharedMemorySize, SMEM_SCORES);
    cudaFuncSetAttribute(attn_pv_kernel,
                         cudaFuncAttributeMaxDynamicSharedMemorySize, SMEM_PV);

    /* QKV: one launch (64x128 tiles, grid 768) */
    mma_gemm<64, EPI_QKV><<<dim3(4, 64, 3), 256, SMEM_G64>>>(
        x, wq_w, wk_w, wv_w, wq_b, wk_b, wv_b, pq, pk, pv,
        BT, D_MODEL, D_MODEL, D_MODEL, D_MODEL, D_MODEL);

    /* scores -> fp16 expS (half the store bytes) + partial row sums */
    scores_kernel<<<dim3(16, 16, BH), 256, SMEM_SCORES>>>(pq, pk, pexp, ppsum);

    /* psum reduce + fp16->fp32 + normalize + attn write + ctx = P @ V */
    attn_pv_kernel<<<dim3(T_SEQ / 64, BH), 256, SMEM_PV>>>(
        pexp, pv, ppsum, attn, pctx);

    /* output projection + LN1 */
    mma_gemm<64, EPI_BIAS><<<dim3(4, 64, 1), 256, SMEM_G64>>>(
        pctx, wo_w, wo_w, wo_w, wo_b, wo_b, wo_b, ptmp, ptmp, ptmp,
        BT, D_MODEL, D_MODEL, D_MODEL, D_MODEL, D_MODEL);
    add_ln_kernel<<<BT, 128>>>(x, ptmp, ln1_g, ln1_b, ph);

    /* FFN + LN2 (FC1 128x128, FC2 64x128) */
    mma_gemm<128, EPI_RELU><<<dim3(16, 32, 1), 256, SMEM_G128>>>(
        ph, fc1_w, fc1_w, fc1_w, fc1_b, fc1_b, fc1_b, pffn1, pffn1, pffn1,
        BT, D_FF, D_MODEL, D_MODEL, D_FF, D_FF);
    mma_gemm<64, EPI_BIAS><<<dim3(4, 64, 1), 256, SMEM_G64>>>(
        pffn1, fc2_w, fc2_w, fc2_w, fc2_b, fc2_b, fc2_b, ptmp, ptmp, ptmp,
        BT, D_MODEL, D_FF, D_FF, D_MODEL, D_MODEL);
    add_ln_kernel<<<BT, 128>>>(ph, ptmp, ln2_g, ln2_b, out);
}

// round 15
// speedup vs baseline: 1.9481x; 1.0544x over previous
#include <cuda_runtime.h>
#include <cuda_fp16.h>
#include <math.h>
#include <stdint.h>

#define D_MODEL 512
#define N_HEADS 8
#define D_KK    64
#define D_FF    2048
#define T_SEQ   2048
#define B_BATCH 2
#define BT      (B_BATCH * T_SEQ)
#define BH      (B_BATCH * N_HEADS)

#define OUT_ELEMS  ((size_t)BT * D_MODEL)
#define ATTN_ELEMS ((size_t)BH * T_SEQ * T_SEQ)

#define EPI_BIAS   0
#define EPI_RELU   1
#define EPI_QKV    2

#define LOG2E 1.4426950408889634f

/* ---------------- scratch ------------------------------------------------- */
__device__ float  g_q[BH * T_SEQ * D_KK];
__device__ float  g_k[BH * T_SEQ * D_KK];
__device__ float  g_v[BH * T_SEQ * D_KK];
__device__ float  g_ctx[BT * D_MODEL];
__device__ float  g_tmp[BT * D_MODEL];
__device__ float  g_h[BT * D_MODEL];
__device__ float  g_ffn1[BT * D_FF];
__device__ float  g_psum[(size_t)BH * T_SEQ * 32];
__device__ __half g_expS[(size_t)BH * T_SEQ * T_SEQ];   /* fp16 intermediate */
__device__ float  g_attn_scratch[BH * (size_t)T_SEQ * T_SEQ];

/* ---------------- helpers ------------------------------------------------- */
/* RZ tf32 (dense GEMM mainloops): raw fp32 bits. */
__device__ __forceinline__ uint32_t f2tf(float f) { return __float_as_uint(f); }
/* RN tf32 (scores QK^T): accuracy headroom for fp16 quantization. */
__device__ __forceinline__ uint32_t f2tfr(float f) {
    uint32_t r;
    asm("cvt.rna.tf32.f32 %0, %1;" : "=r"(r) : "f"(f));
    return r;
}
__device__ __forceinline__ float ex2(float x) {
    float r;
    asm("ex2.approx.f32 %0, %1;" : "=f"(r) : "f"(x));
    return r;
}
__device__ __forceinline__ void mma8(float c[4], uint32_t a0, uint32_t a1,
                                     uint32_t a2, uint32_t a3,
                                     uint32_t b0, uint32_t b1) {
    asm volatile(
        "mma.sync.aligned.m16n8k8.row.col.f32.tf32.tf32.f32 "
        "{%0,%1,%2,%3}, {%4,%5,%6,%7}, {%8,%9}, {%0,%1,%2,%3};"
        : "+f"(c[0]), "+f"(c[1]), "+f"(c[2]), "+f"(c[3])
        : "r"(a0), "r"(a1), "r"(a2), "r"(a3), "r"(b0), "r"(b1));
}
/* fp16 MMA m16n8k16 with fp32 accumulate (PV matmul) */
__device__ __forceinline__ void mma16h(float c[4], uint32_t a0, uint32_t a1,
                                       uint32_t a2, uint32_t a3,
                                       uint32_t b0, uint32_t b1) {
    asm volatile(
        "mma.sync.aligned.m16n8k16.row.col.f32.f16.f16.f32 "
        "{%0,%1,%2,%3}, {%4,%5,%6,%7}, {%8,%9}, {%0,%1,%2,%3};"
        : "+f"(c[0]), "+f"(c[1]), "+f"(c[2]), "+f"(c[3])
        : "r"(a0), "r"(a1), "r"(a2), "r"(a3), "r"(b0), "r"(b1));
}
__device__ __forceinline__ void cp16(void* sdst, const void* gsrc) {
    uint32_t s = (uint32_t)__cvta_generic_to_shared(sdst);
    asm volatile("cp.async.cg.shared.global [%0], [%1], 16;" :: "r"(s), "l"(gsrc));
}
__device__ __forceinline__ float warp_sum(float v) {
    #pragma unroll
    for (int o = 16; o > 0; o >>= 1) v += __shfl_xor_sync(0xffffffffu, v, o);
    return v;
}

/* ---------------- cp.async double-buffered tf32 GEMM (R8 shapes) ---------- */
template <int BM, int EPI>
__global__ __launch_bounds__(256) void mma_gemm(
    const float* __restrict__ A,
    const float* __restrict__ B0, const float* __restrict__ B1, const float* __restrict__ B2,
    const float* __restrict__ bias0, const float* __restrict__ bias1, const float* __restrict__ bias2,
    float* __restrict__ C0, float* __restrict__ C1, float* __restrict__ C2,
    int M, int N, int K, int lda, int ldb, int ldc)
{
    constexpr int KT  = 32;
    constexpr int SA  = KT + 4;                  /* 36  */
    constexpr int SBk = 128 + 8;                 /* 136 */
    constexpr int A_ELE = BM * SA;
    constexpr int B_ELE = KT * SBk;
    constexpr int STG = A_ELE + B_ELE;
    constexpr int AN = (BM == 128) ? 8 : 4;

    extern __shared__ float smem[];

    const int tid = threadIdx.x;
    const int lane = tid & 31, wid = tid >> 5;
    const int z = blockIdx.z;
    const float* B    = (z == 0) ? B0 : (z == 1) ? B1 : B2;
    const float* bias = (z == 0) ? bias0 : (z == 1) ? bias1 : bias2;
    float* C          = (z == 0) ? C0 : (z == 1) ? C1 : C2;

    const int bm = blockIdx.y * BM;
    const int bn = blockIdx.x * 128;
    const int mb = (BM == 128) ? (wid & 3) * 32 : (wid & 1) * 32;
    const int nb = (BM == 128) ? (wid >> 2) * 64 : (wid >> 1) * 32;

    float acc[2][AN][4];
    #pragma unroll
    for (int i = 0; i < 2; i++)
        #pragma unroll
        for (int j = 0; j < AN; j++)
            #pragma unroll
            for (int r = 0; r < 4; r++) acc[i][j][r] = 0.0f;

    auto issue = [&](int k0, int st) {
        float* As = smem + st * STG;
        float* Bs = As + A_ELE;
        #pragma unroll
        for (int i = 0; i < BM * KT / 1024; i++) {
            int f = tid + i * 256;
            int m = f >> 3, k4 = (f & 7) * 4;
            cp16(&As[m * SA + k4], &A[(size_t)(bm + m) * lda + k0 + k4]);
        }
        #pragma unroll
        for (int i = 0; i < 4; i++) {
            int f = tid + i * 256;
            int kk = f >> 5, n4 = (f & 31) * 4;
            cp16(&Bs[kk * SBk + n4], &B[(size_t)(k0 + kk) * ldb + bn + n4]);
        }
        asm volatile("cp.async.commit_group;" ::: "memory");
    };

    issue(0, 0);
    const int nIter = K / KT;
    for (int it = 0; it < nIter; it++) {
        if (it + 1 < nIter) {
            issue((it + 1) * KT, (it + 1) & 1);
            asm volatile("cp.async.wait_group 1;" ::: "memory");
        } else {
            asm volatile("cp.async.wait_group 0;" ::: "memory");
        }
        __syncthreads();

        float* As = smem + (it & 1) * STG;
        float* Bs = As + A_ELE;
        #pragma unroll
        for (int ks = 0; ks < KT / 8; ks++) {
            uint32_t af[2][4], bf[AN][2];
            #pragma unroll
            for (int am = 0; am < 2; am++)
                #pragma unroll
                for (int j = 0; j < 4; j++)
                    af[am][j] = f2tf(As[(mb + am * 16 + (lane >> 2) + (j & 1) * 8) * SA
                                        + ks * 8 + (lane & 3) + (j >> 1) * 4]);
            #pragma unroll
            for (int an = 0; an < AN; an++)
                #pragma unroll
                for (int j = 0; j < 2; j++)
                    bf[an][j] = f2tf(Bs[(ks * 8 + (lane & 3) + j * 4) * SBk
                                        + nb + an * 8 + (lane >> 2)]);
            #pragma unroll
            for (int am = 0; am < 2; am++)
                #pragma unroll
                for (int an = 0; an < AN; an++)
                    mma8(acc[am][an], af[am][0], af[am][1], af[am][2], af[am][3],
                         bf[an][0], bf[an][1]);
        }
        __syncthreads();
    }

    #pragma unroll
    for (int am = 0; am < 2; am++)
        #pragma unroll
        for (int an = 0; an < AN; an++)
            #pragma unroll
            for (int half = 0; half < 2; half++) {
                int m = bm + mb + am * 16 + (lane >> 2) + half * 8;
                int c = bn + nb + an * 8 + (lane & 3) * 2;
                float v0 = acc[am][an][half * 2 + 0] + bias[c];
                float v1 = acc[am][an][half * 2 + 1] + bias[c + 1];
                if (EPI == EPI_RELU) { v0 = fmaxf(v0, 0.0f); v1 = fmaxf(v1, 0.0f); }
                if (EPI == EPI_QKV) {
                    int bb = m >> 11, t = m & (T_SEQ - 1);
                    int h = c >> 6, d = c & (D_KK - 1);
                    *(float2*)&C[((size_t)((bb * N_HEADS + h) * T_SEQ) + t) * D_KK + d]
                        = make_float2(v0, v1);
                } else {
                    *(float2*)&C[(size_t)m * ldc + c] = make_float2(v0, v1);
                }
            }
}

/* ---------------- scores: expS(fp16) <- exp2(QK^T * sc), partial sums ----- */
__global__ __launch_bounds__(256) void scores_kernel(
    const float* __restrict__ Q, const float* __restrict__ K,
    __half* __restrict__ expS, float* __restrict__ psum)
{
    constexpr int S = 68;
    extern __shared__ float sm[];
    float* Qs = sm;              /* [128][68] */
    float* Ks = sm + 128 * S;    /* [128][68] */

    const int tid = threadIdx.x;
    const int lane = tid & 31, wid = tid >> 5;
    const int z = blockIdx.z;
    const int bm = blockIdx.y * 128;
    const int bn = blockIdx.x * 128;
    Q += (size_t)z * T_SEQ * D_KK;
    K += (size_t)z * T_SEQ * D_KK;

    #pragma unroll
    for (int i = 0; i < 8; i++) {
        int f = tid + i * 256;
        int m = f >> 4, k4 = (f & 15) * 4;
        cp16(&Qs[m * S + k4], &Q[(size_t)(bm + m) * D_KK + k4]);
        cp16(&Ks[m * S + k4], &K[(size_t)(bn + m) * D_KK + k4]);
    }
    asm volatile("cp.async.commit_group;" ::: "memory");
    asm volatile("cp.async.wait_group 0;" ::: "memory");
    __syncthreads();

    const int mb = (wid & 3) * 32;
    const int nwarp = wid >> 2;
    const int nb = nwarp * 64;

    float acc[2][8][4];
    #pragma unroll
    for (int i = 0; i < 2; i++)
        #pragma unroll
        for (int j = 0; j < 8; j++)
            #pragma unroll
            for (int r = 0; r < 4; r++) acc[i][j][r] = 0.0f;

    #pragma unroll
    for (int ks = 0; ks < 8; ks++) {
        uint32_t af[2][4], bf[8][2];
        #pragma unroll
        for (int am = 0; am < 2; am++)
            #pragma unroll
            for (int j = 0; j < 4; j++)
                af[am][j] = f2tfr(Qs[(mb + am * 16 + (lane >> 2) + (j & 1) * 8) * S
                                     + ks * 8 + (lane & 3) + (j >> 1) * 4]);
        #pragma unroll
        for (int an = 0; an < 8; an++)
            #pragma unroll
            for (int j = 0; j < 2; j++)
                bf[an][j] = f2tfr(Ks[(nb + an * 8 + (lane >> 2)) * S
                                     + ks * 8 + (lane & 3) + j * 4]);
        #pragma unroll
        for (int am = 0; am < 2; am++)
            #pragma unroll
            for (int an = 0; an < 8; an++)
                mma8(acc[am][an], af[am][0], af[am][1], af[am][2], af[am][3],
                     bf[an][0], bf[an][1]);
    }

    const float sc = 0.125f * LOG2E;
    __half* Ez = expS + (size_t)z * T_SEQ * T_SEQ;
    #pragma unroll
    for (int am = 0; am < 2; am++)
        #pragma unroll
        for (int half = 0; half < 2; half++) {
            int m = bm + mb + am * 16 + (lane >> 2) + half * 8;
            float rs = 0.0f;
            #pragma unroll
            for (int an = 0; an < 8; an++) {
                int c = bn + nb + an * 8 + (lane & 3) * 2;
                float e0 = ex2(acc[am][an][half * 2 + 0] * sc);
                float e1 = ex2(acc[am][an][half * 2 + 1] * sc);
                __half2 hv = __floats2half2_rn(e0, e1);
                *(__half2*)&Ez[(size_t)m * T_SEQ + c] = hv;
                float2 qv = __half22float2(hv);   /* sum the quantized values */
                rs += qv.x + qv.y;
            }
            rs += __shfl_xor_sync(0xffffffffu, rs, 1);
            rs += __shfl_xor_sync(0xffffffffu, rs, 2);
            if ((lane & 3) == 0)
                psum[((size_t)z * T_SEQ + m) * 32 + blockIdx.x * 2 + nwarp] = rs;
        }
}

/* ---------------- fused psum-reduce + normalize + attn write + P@V --------
 * BM=64 stripe; KT=64 2-stage (R8 skeleton). P kept in fp16 smem and fed
 * straight into m16n8k16 fp16 MMA (no fp32 staging); V frags cvt fp32->fp16.
 * P smem stride 72 halves (36 words: bank = 4r+c, cf-free); V stride 68
 * (bank = 4k+n over k in {0,2,4,6}, cf-free).
 */
__global__ __launch_bounds__(256, 3) void attn_pv_kernel(
    const __half* __restrict__ expS, const float* __restrict__ V,
    const float* __restrict__ psum, float* __restrict__ attn,
    float* __restrict__ ctx)
{
    constexpr int KT  = 64;
    constexpr int BM  = 64;
    constexpr int SPH = 72;                    /* P stride in halves */
    constexpr int SV  = 68;                    /* V stride in floats */
    constexpr int PH_W = BM * SPH / 2;         /* 2304 words per stage */
    constexpr int VS_W = KT * SV;              /* 4352 words per stage */
    constexpr int STG  = PH_W + VS_W;          /* 6656 words */
    extern __shared__ float sm[];
    float* invs = sm + 2 * STG;

    const int tid = threadIdx.x;
    const int lane = tid & 31, wid = tid >> 5;
    const int bm = blockIdx.x * BM;
    const int z = blockIdx.y;
    expS += (size_t)z * T_SEQ * T_SEQ;
    V    += (size_t)z * T_SEQ * D_KK;
    attn += (size_t)z * T_SEQ * T_SEQ;

    auto issue = [&](int k0, int st) {
        __half* Ph = (__half*)(sm + st * STG);
        float*  Vs = sm + st * STG + PH_W;
        #pragma unroll
        for (int i = 0; i < 2; i++) {          /* 64x64 halves = 512 x 16B */
            int f = tid + i * 256;
            int m = f >> 3, k8 = (f & 7) * 8;
            cp16(&Ph[m * SPH + k8], &expS[(size_t)(bm + m) * T_SEQ + k0 + k8]);
        }
        #pragma unroll
        for (int i = 0; i < 4; i++) {
            int f = tid + i * 256;
            int kk = f >> 4, c4 = (f & 15) * 4;
            cp16(&Vs[kk * SV + c4], &V[(size_t)(k0 + kk) * D_KK + c4]);
        }
        asm volatile("cp.async.commit_group;" ::: "memory");
    };

    issue(0, 0);

    /* reduce this stripe's psums -> invs (CTA exclusively owns rows) */
    if (tid < BM) {
        const float4* p = (const float4*)(psum + ((size_t)z * T_SEQ + bm + tid) * 32);
        float s = 0.0f;
        #pragma unroll
        for (int i = 0; i < 8; i++) {
            float4 v = p[i];
            s += v.x + v.y + v.z + v.w;
        }
        invs[tid] = 1.0f / s;
    }
    __syncthreads();

    const int mb = (wid & 1) * 32;
    const int nb = (wid >> 1) * 16;

    float acc[2][2][4];
    #pragma unroll
    for (int i = 0; i < 2; i++)
        #pragma unroll
        for (int j = 0; j < 2; j++)
            #pragma unroll
            for (int r = 0; r < 4; r++) acc[i][j][r] = 0.0f;

    const int nIter = T_SEQ / KT;   /* 32 */
    for (int it = 0; it < nIter; it++) {
        if (it + 1 < nIter) {
            issue((it + 1) * KT, (it + 1) & 1);
            asm volatile("cp.async.wait_group 1;" ::: "memory");
        } else {
            asm volatile("cp.async.wait_group 0;" ::: "memory");
        }
        __syncthreads();

        const uint32_t* ph2 = (const uint32_t*)(sm + (it & 1) * STG); /* half2 view, stride 36 */
        const float*    Vs  = sm + (it & 1) * STG + PH_W;

        #pragma unroll
        for (int ks = 0; ks < KT / 16; ks++) {   /* 4 k16 steps */
            uint32_t af[2][4], bf[2][2];
            #pragma unroll
            for (int am = 0; am < 2; am++)
                #pragma unroll
                for (int j = 0; j < 4; j++)
                    af[am][j] = ph2[(mb + am * 16 + (lane >> 2) + (j & 1) * 8) * 36
                                    + ks * 8 + 4 * (j >> 1) + (lane & 3)];
            #pragma unroll
            for (int an = 0; an < 2; an++)
                #pragma unroll
                for (int j = 0; j < 2; j++) {
                    int kk = ks * 16 + 2 * (lane & 3) + 8 * j;
                    int n = nb + an * 8 + (lane >> 2);
                    __half2 hv = __floats2half2_rn(Vs[kk * SV + n],
                                                   Vs[(kk + 1) * SV + n]);
                    bf[an][j] = *reinterpret_cast<uint32_t*>(&hv);
                }
            #pragma unroll
            for (int am = 0; am < 2; am++)
                #pragma unroll
                for (int an = 0; an < 2; an++)
                    mma16h(acc[am][an], af[am][0], af[am][1], af[am][2], af[am][3],
                           bf[an][0], bf[an][1]);
        }

        /* normalized attn write: fp16 smem -> fp32 gmem (coalesced) */
        {
            const uint32_t* p2 = (const uint32_t*)(sm + (it & 1) * STG);
            #pragma unroll
            for (int i = 0; i < 8; i++) {        /* 2048 half2 / 256 thr */
                int idx = tid + i * 256;
                int m = idx >> 5, c2 = idx & 31; /* half2 index within row */
                uint32_t u = p2[m * 36 + c2];
                float2 fv = __half22float2(*reinterpret_cast<__half2*>(&u));
                float iv = invs[m];
                fv.x *= iv; fv.y *= iv;
                *(float2*)&attn[(size_t)(bm + m) * T_SEQ + it * KT + c2 * 2] = fv;
            }
        }
        __syncthreads();
    }

    const int b = z >> 3, h = z & 7;
    float* Cz = ctx + (size_t)b * T_SEQ * D_MODEL + h * D_KK;
    #pragma unroll
    for (int am = 0; am < 2; am++)
        #pragma unroll
        for (int an = 0; an < 2; an++)
            #pragma unroll
            for (int half = 0; half < 2; half++) {
                int mr = mb + am * 16 + (lane >> 2) + half * 8;
                int c = nb + an * 8 + (lane & 3) * 2;
                float iv = invs[mr];
                *(float2*)&Cz[(size_t)(bm + mr) * D_MODEL + c]
                    = make_float2(acc[am][an][half * 2 + 0] * iv,
                                  acc[am][an][half * 2 + 1] * iv);
            }
}

/* ---------------- fused residual add + LayerNorm ------------------------- */
__global__ __launch_bounds__(128) void add_ln_kernel(
    const float* __restrict__ X, const float* __restrict__ Y,
    const float* __restrict__ g, const float* __restrict__ b,
    float* __restrict__ O)
{
    const int tid = threadIdx.x;
    const size_t base = (size_t)blockIdx.x * D_MODEL + tid * 4;
    float4 xv = *(const float4*)&X[base];
    float4 yv = *(const float4*)&Y[base];
    float4 v = make_float4(xv.x + yv.x, xv.y + yv.y, xv.z + yv.z, xv.w + yv.w);

    float s  = v.x + v.y + v.z + v.w;
    float ss = v.x * v.x + v.y * v.y + v.z * v.z + v.w * v.w;
    s = warp_sum(s);
    ss = warp_sum(ss);

    __shared__ float r1[4], r2[4];
    const int wid = tid >> 5, lane = tid & 31;
    if (lane == 0) { r1[wid] = s; r2[wid] = ss; }
    __syncthreads();
    if (tid == 0) {
        float a = 0.0f, c = 0.0f;
        #pragma unroll
        for (int i = 0; i < 4; i++) { a += r1[i]; c += r2[i]; }
        r1[0] = a; r2[0] = c;
    }
    __syncthreads();
    const float mu  = r1[0] * (1.0f / 512.0f);
    const float var = r2[0] * (1.0f / 512.0f) - mu * mu;
    const float rs  = rsqrtf(var + 1e-5f);

    float4 gv = *(const float4*)&g[tid * 4];
    float4 bv = *(const float4*)&b[tid * 4];
    float4 o;
    o.x = (v.x - mu) * rs * gv.x + bv.x;
    o.y = (v.y - mu) * rs * gv.y + bv.y;
    o.z = (v.z - mu) * rs * gv.z + bv.z;
    o.w = (v.w - mu) * rs * gv.w + bv.w;
    *(float4*)&O[base] = o;
}

/* ---------------- launch -------------------------------------------------- */
#define SMEM_G128   71680   /* 2*(128*36 + 32*136)*4 */
#define SMEM_G64    53248   /* 2*( 64*36 + 32*136)*4 */
#define SMEM_SCORES 69632   /* 2*128*68*4 */
#define SMEM_PV     53504   /* (2*6656 + 64)*4 */

extern "C" void kernel_launch(void* const* d_in, const int* in_sizes, int n_in,
                              void* d_out, int out_size)
{
    const float* x     = (const float*)d_in[0];
    const float* wq_w  = (const float*)d_in[1];
    const float* wq_b  = (const float*)d_in[2];
    const float* wk_w  = (const float*)d_in[3];
    const float* wk_b  = (const float*)d_in[4];
    const float* wv_w  = (const float*)d_in[5];
    const float* wv_b  = (const float*)d_in[6];
    const float* wo_w  = (const float*)d_in[7];
    const float* wo_b  = (const float*)d_in[8];
    const float* ln1_g = (const float*)d_in[9];
    const float* ln1_b = (const float*)d_in[10];
    const float* fc1_w = (const float*)d_in[11];
    const float* fc1_b = (const float*)d_in[12];
    const float* fc2_w = (const float*)d_in[13];
    const float* fc2_b = (const float*)d_in[14];
    const float* ln2_g = (const float*)d_in[15];
    const float* ln2_b = (const float*)d_in[16];

    float* out = (float*)d_out;

    float *pq, *pk, *pv, *pctx, *ptmp, *ph, *pffn1, *ppsum;
    __half* pexp;
    cudaGetSymbolAddress((void**)&pq,    g_q);
    cudaGetSymbolAddress((void**)&pk,    g_k);
    cudaGetSymbolAddress((void**)&pv,    g_v);
    cudaGetSymbolAddress((void**)&pctx,  g_ctx);
    cudaGetSymbolAddress((void**)&ptmp,  g_tmp);
    cudaGetSymbolAddress((void**)&ph,    g_h);
    cudaGetSymbolAddress((void**)&pffn1, g_ffn1);
    cudaGetSymbolAddress((void**)&ppsum, g_psum);
    cudaGetSymbolAddress((void**)&pexp,  g_expS);

    float* attn;
    if ((size_t)out_size >= OUT_ELEMS + ATTN_ELEMS) {
        attn = out + OUT_ELEMS;
    } else {
        cudaGetSymbolAddress((void**)&attn, g_attn_scratch);
    }

    cudaFuncSetAttribute(mma_gemm<64, EPI_QKV>,
                         cudaFuncAttributeMaxDynamicSharedMemorySize, SMEM_G64);
    cudaFuncSetAttribute(mma_gemm<64, EPI_BIAS>,
                         cudaFuncAttributeMaxDynamicSharedMemorySize, SMEM_G64);
    cudaFuncSetAttribute(mma_gemm<128, EPI_RELU>,
                         cudaFuncAttributeMaxDynamicSharedMemorySize, SMEM_G128);
    cudaFuncSetAttribute(scores_kernel,
                         cudaFuncAttributeMaxDynamicSharedMemorySize, SMEM_SCORES);
    cudaFuncSetAttribute(attn_pv_kernel,
                         cudaFuncAttributeMaxDynamicSharedMemorySize, SMEM_PV);

    /* QKV: one launch (64x128 tiles, grid 768) */
    mma_gemm<64, EPI_QKV><<<dim3(4, 64, 3), 256, SMEM_G64>>>(
        x, wq_w, wk_w, wv_w, wq_b, wk_b, wv_b, pq, pk, pv,
        BT, D_MODEL, D_MODEL, D_MODEL, D_MODEL, D_MODEL);

    /* scores -> fp16 expS (half the store bytes) + partial row sums */
    scores_kernel<<<dim3(16, 16, BH), 256, SMEM_SCORES>>>(pq, pk, pexp, ppsum);

    /* psum reduce + normalize + attn write + ctx = P @ V (fp16 MMA) */
    attn_pv_kernel<<<dim3(T_SEQ / 64, BH), 256, SMEM_PV>>>(
        pexp, pv, ppsum, attn, pctx);

    /* output projection + LN1 */
    mma_gemm<64, EPI_BIAS><<<dim3(4, 64, 1), 256, SMEM_G64>>>(
        pctx, wo_w, wo_w, wo_w, wo_b, wo_b, wo_b, ptmp, ptmp, ptmp,
        BT, D_MODEL, D_MODEL, D_MODEL, D_MODEL, D_MODEL);
    add_ln_kernel<<<BT, 128>>>(x, ptmp, ln1_g, ln1_b, ph);

    /* FFN + LN2 (FC1 128x128, FC2 64x128) */
    mma_gemm<128, EPI_RELU><<<dim3(16, 32, 1), 256, SMEM_G128>>>(
        ph, fc1_w, fc1_w, fc1_w, fc1_b, fc1_b, fc1_b, pffn1, pffn1, pffn1,
        BT, D_FF, D_MODEL, D_MODEL, D_FF, D_FF);
    mma_gemm<64, EPI_BIAS><<<dim3(4, 64, 1), 256, SMEM_G64>>>(
        pffn1, fc2_w, fc2_w, fc2_w, fc2_b, fc2_b, fc2_b, ptmp, ptmp, ptmp,
        BT, D_MODEL, D_FF, D_FF, D_MODEL, D_MODEL);
    add_ln_kernel<<<BT, 128>>>(ph, ptmp, ln2_g, ln2_b, out);
}

// round 16
// speedup vs baseline: 2.3812x; 1.2223x over previous
#include <cuda_runtime.h>
#include <cuda_fp16.h>
#include <math.h>
#include <stdint.h>

#define D_MODEL 512
#define N_HEADS 8
#define D_KK    64
#define D_FF    2048
#define T_SEQ   2048
#define B_BATCH 2
#define BT      (B_BATCH * T_SEQ)
#define BH      (B_BATCH * N_HEADS)

#define OUT_ELEMS  ((size_t)BT * D_MODEL)
#define ATTN_ELEMS ((size_t)BH * T_SEQ * T_SEQ)

#define EPI_BIAS   0   /* fp32 out */
#define EPI_RELU_H 1   /* relu, fp16 out */
#define EPI_QKV    2   /* q/k fp16 [t][d]; v fp16 [d][t] */

#define LOG2E 1.4426950408889634f

/* ---------------- scratch ------------------------------------------------- */
__device__ __half g_xh[BT * D_MODEL];
__device__ __half g_qh[BH * T_SEQ * D_KK];
__device__ __half g_kh[BH * T_SEQ * D_KK];
__device__ __half g_vth[BH * D_KK * T_SEQ];          /* V transposed [d][t] */
__device__ __half g_ctxh[BT * D_MODEL];
__device__ __half g_hh[BT * D_MODEL];
__device__ __half g_ffn1h[BT * D_FF];
__device__ __half g_wqt[D_MODEL * D_MODEL];
__device__ __half g_wkt[D_MODEL * D_MODEL];
__device__ __half g_wvt[D_MODEL * D_MODEL];
__device__ __half g_wot[D_MODEL * D_MODEL];
__device__ __half g_fc1t[D_FF * D_MODEL];            /* [N=2048][K=512] */
__device__ __half g_fc2t[D_MODEL * D_FF];            /* [N=512][K=2048] */
__device__ float  g_tmp[BT * D_MODEL];
__device__ float  g_h[BT * D_MODEL];
__device__ float  g_psum[(size_t)BH * T_SEQ * 32];
__device__ __half g_expS[(size_t)BH * T_SEQ * T_SEQ];
__device__ float  g_attn_scratch[BH * (size_t)T_SEQ * T_SEQ];

/* ---------------- helpers ------------------------------------------------- */
__device__ __forceinline__ float ex2(float x) {
    float r;
    asm("ex2.approx.f32 %0, %1;" : "=f"(r) : "f"(x));
    return r;
}
__device__ __forceinline__ void mma16h(float c[4], uint32_t a0, uint32_t a1,
                                       uint32_t a2, uint32_t a3,
                                       uint32_t b0, uint32_t b1) {
    asm volatile(
        "mma.sync.aligned.m16n8k16.row.col.f32.f16.f16.f32 "
        "{%0,%1,%2,%3}, {%4,%5,%6,%7}, {%8,%9}, {%0,%1,%2,%3};"
        : "+f"(c[0]), "+f"(c[1]), "+f"(c[2]), "+f"(c[3])
        : "r"(a0), "r"(a1), "r"(a2), "r"(a3), "r"(b0), "r"(b1));
}
__device__ __forceinline__ void cp16(void* sdst, const void* gsrc) {
    uint32_t s = (uint32_t)__cvta_generic_to_shared(sdst);
    asm volatile("cp.async.cg.shared.global [%0], [%1], 16;" :: "r"(s), "l"(gsrc));
}
__device__ __forceinline__ float warp_sum(float v) {
    #pragma unroll
    for (int o = 16; o > 0; o >>= 1) v += __shfl_xor_sync(0xffffffffu, v, o);
    return v;
}

/* ---------------- converts ------------------------------------------------ */
__global__ __launch_bounds__(256) void f2h_kernel(
    const float* __restrict__ s, __half* __restrict__ d)
{
    int i = blockIdx.x * 256 + threadIdx.x;
    float2 v = ((const float2*)s)[i];
    ((__half2*)d)[i] = __floats2half2_rn(v.x, v.y);
}

/* W [K][N] fp32 -> Wt [N][K] fp16 */
__global__ __launch_bounds__(256) void transpose_h(
    const float* __restrict__ W, __half* __restrict__ Wt, int K, int N)
{
    __shared__ float t[32][33];
    int n0 = blockIdx.x * 32, k0 = blockIdx.y * 32;
    int tx = threadIdx.x & 31, ty = threadIdx.x >> 5;   /* 32 x 8 */
    #pragma unroll
    for (int i = 0; i < 4; i++)
        t[ty + i * 8][tx] = W[(size_t)(k0 + ty + i * 8) * N + n0 + tx];
    __syncthreads();
    #pragma unroll
    for (int i = 0; i < 4; i++)
        Wt[(size_t)(n0 + ty + i * 8) * K + k0 + tx]
            = __float2half_rn(t[tx][ty + i * 8]);
}

/* ---------------- fp16 cp.async double-buffered GEMM ----------------------
 * C[M,128-col tile] = A[M,K](fp16 row-major) @ Wt[N,K](fp16) + bias.
 * Tile BM x 128 x 32. Smem rows 40 halves (20 words): fragment banks
 * (20m + c) cover all 32 (verified).
 */
template <int BM, int EPI>
__global__ __launch_bounds__(256) void mma_gemm_h(
    const __half* __restrict__ A,
    const __half* __restrict__ B0, const __half* __restrict__ B1, const __half* __restrict__ B2,
    const float* __restrict__ bias0, const float* __restrict__ bias1, const float* __restrict__ bias2,
    void* __restrict__ C0, void* __restrict__ C1, void* __restrict__ C2,
    int K, int lda, int ldb, int ldc)
{
    constexpr int SW  = 20;                    /* words per smem row */
    constexpr int A_W = BM * SW;
    constexpr int B_W = 128 * SW;
    constexpr int STG = A_W + B_W;
    constexpr int AN  = (BM == 128) ? 8 : 4;

    extern __shared__ uint32_t smh[];

    const int tid = threadIdx.x;
    const int lane = tid & 31, wid = tid >> 5;
    const int r0 = lane >> 2;
    const int z = blockIdx.z;
    const __half* B   = (z == 0) ? B0 : (z == 1) ? B1 : B2;
    const float* bias = (z == 0) ? bias0 : (z == 1) ? bias1 : bias2;
    void* C           = (z == 0) ? C0 : (z == 1) ? C1 : C2;

    const int bm = blockIdx.y * BM;
    const int bn = blockIdx.x * 128;
    const int mb = (BM == 128) ? (wid & 3) * 32 : (wid & 1) * 32;
    const int nb = (BM == 128) ? (wid >> 2) * 64 : (wid >> 1) * 32;

    float acc[2][AN][4];
    #pragma unroll
    for (int i = 0; i < 2; i++)
        #pragma unroll
        for (int j = 0; j < AN; j++)
            #pragma unroll
            for (int r = 0; r < 4; r++) acc[i][j][r] = 0.0f;

    auto issue = [&](int k0, int st) {
        __half* Ah = (__half*)(smh + st * STG);
        __half* Bh = (__half*)(smh + st * STG + A_W);
        #pragma unroll
        for (int i = 0; i < BM * 4 / 256; i++) {
            int f = tid + i * 256;
            int m = f >> 2, k8 = (f & 3) * 8;
            cp16(&Ah[m * 40 + k8], &A[(size_t)(bm + m) * lda + k0 + k8]);
        }
        #pragma unroll
        for (int i = 0; i < 2; i++) {
            int f = tid + i * 256;
            int n = f >> 2, k8 = (f & 3) * 8;
            cp16(&Bh[n * 40 + k8], &B[(size_t)(bn + n) * ldb + k0 + k8]);
        }
        asm volatile("cp.async.commit_group;" ::: "memory");
    };

    issue(0, 0);
    const int nIter = K / 32;
    for (int it = 0; it < nIter; it++) {
        if (it + 1 < nIter) {
            issue((it + 1) * 32, (it + 1) & 1);
            asm volatile("cp.async.wait_group 1;" ::: "memory");
        } else {
            asm volatile("cp.async.wait_group 0;" ::: "memory");
        }
        __syncthreads();

        const uint32_t* A2 = smh + (it & 1) * STG;
        const uint32_t* B2 = A2 + A_W;
        #pragma unroll
        for (int ks = 0; ks < 2; ks++) {
            uint32_t af[2][4], bf[AN][2];
            #pragma unroll
            for (int am = 0; am < 2; am++)
                #pragma unroll
                for (int j = 0; j < 4; j++)
                    af[am][j] = A2[(mb + am * 16 + r0 + (j & 1) * 8) * SW
                                   + ks * 8 + (lane & 3) + (j >> 1) * 4];
            #pragma unroll
            for (int an = 0; an < AN; an++)
                #pragma unroll
                for (int j = 0; j < 2; j++)
                    bf[an][j] = B2[(nb + an * 8 + r0) * SW
                                   + ks * 8 + (lane & 3) + j * 4];
            #pragma unroll
            for (int am = 0; am < 2; am++)
                #pragma unroll
                for (int an = 0; an < AN; an++)
                    mma16h(acc[am][an], af[am][0], af[am][1], af[am][2], af[am][3],
                           bf[an][0], bf[an][1]);
        }
        __syncthreads();
    }

    #pragma unroll
    for (int am = 0; am < 2; am++)
        #pragma unroll
        for (int an = 0; an < AN; an++)
            #pragma unroll
            for (int half = 0; half < 2; half++) {
                int m = bm + mb + am * 16 + r0 + half * 8;
                int c = bn + nb + an * 8 + (lane & 3) * 2;
                float v0 = acc[am][an][half * 2 + 0] + bias[c];
                float v1 = acc[am][an][half * 2 + 1] + bias[c + 1];
                if (EPI == EPI_BIAS) {
                    *(float2*)&((float*)C)[(size_t)m * ldc + c] = make_float2(v0, v1);
                } else if (EPI == EPI_RELU_H) {
                    v0 = fmaxf(v0, 0.0f); v1 = fmaxf(v1, 0.0f);
                    *(__half2*)&((__half*)C)[(size_t)m * ldc + c]
                        = __floats2half2_rn(v0, v1);
                } else { /* EPI_QKV */
                    int bb = m >> 11, t = m & (T_SEQ - 1);
                    int hh = c >> 6, d = c & (D_KK - 1);
                    __half* Ch = (__half*)C;
                    if (z < 2) {
                        *(__half2*)&Ch[((size_t)((bb * N_HEADS + hh) * T_SEQ) + t) * D_KK + d]
                            = __floats2half2_rn(v0, v1);
                    } else { /* V transposed [d][t] */
                        size_t base = (size_t)((bb * N_HEADS + hh) * D_KK);
                        Ch[(base + d) * T_SEQ + t]     = __float2half_rn(v0);
                        Ch[(base + d + 1) * T_SEQ + t] = __float2half_rn(v1);
                    }
                }
            }
}

/* ---------------- scores: expS(fp16) <- exp2(QK^T * sc), psums ------------
 * Q,K fp16 [t][64]. 128x128 tile, K=64 one-shot, 4 k16 steps.
 */
__global__ __launch_bounds__(256) void scores_kernel(
    const __half* __restrict__ Q, const __half* __restrict__ K,
    __half* __restrict__ expS, float* __restrict__ psum)
{
    constexpr int SW = 36;                     /* words per row (72 halves) */
    extern __shared__ uint32_t smh[];
    uint32_t* Q2 = smh;                        /* 128*36 */
    uint32_t* K2 = smh + 128 * SW;

    const int tid = threadIdx.x;
    const int lane = tid & 31, wid = tid >> 5;
    const int r0 = lane >> 2;
    const int z = blockIdx.z;
    const int bm = blockIdx.y * 128;
    const int bn = blockIdx.x * 128;
    Q += (size_t)z * T_SEQ * D_KK;
    K += (size_t)z * T_SEQ * D_KK;

    #pragma unroll
    for (int i = 0; i < 4; i++) {
        int f = tid + i * 256;
        int m = f >> 3, k8 = (f & 7) * 8;
        cp16((__half*)Q2 + m * 72 + k8, &Q[(size_t)(bm + m) * D_KK + k8]);
        cp16((__half*)K2 + m * 72 + k8, &K[(size_t)(bn + m) * D_KK + k8]);
    }
    asm volatile("cp.async.commit_group;" ::: "memory");
    asm volatile("cp.async.wait_group 0;" ::: "memory");
    __syncthreads();

    const int mb = (wid & 3) * 32;
    const int nwarp = wid >> 2;
    const int nb = nwarp * 64;

    float acc[2][8][4];
    #pragma unroll
    for (int i = 0; i < 2; i++)
        #pragma unroll
        for (int j = 0; j < 8; j++)
            #pragma unroll
            for (int r = 0; r < 4; r++) acc[i][j][r] = 0.0f;

    #pragma unroll
    for (int ks = 0; ks < 4; ks++) {
        uint32_t af[2][4], bf[8][2];
        #pragma unroll
        for (int am = 0; am < 2; am++)
            #pragma unroll
            for (int j = 0; j < 4; j++)
                af[am][j] = Q2[(mb + am * 16 + r0 + (j & 1) * 8) * SW
                               + ks * 8 + (lane & 3) + (j >> 1) * 4];
        #pragma unroll
        for (int an = 0; an < 8; an++)
            #pragma unroll
            for (int j = 0; j < 2; j++)
                bf[an][j] = K2[(nb + an * 8 + r0) * SW
                               + ks * 8 + (lane & 3) + j * 4];
        #pragma unroll
        for (int am = 0; am < 2; am++)
            #pragma unroll
            for (int an = 0; an < 8; an++)
                mma16h(acc[am][an], af[am][0], af[am][1], af[am][2], af[am][3],
                       bf[an][0], bf[an][1]);
    }

    const float sc = 0.125f * LOG2E;
    __half* Ez = expS + (size_t)z * T_SEQ * T_SEQ;
    #pragma unroll
    for (int am = 0; am < 2; am++)
        #pragma unroll
        for (int half = 0; half < 2; half++) {
            int m = bm + mb + r0 + am * 16 + half * 8;
            float rs = 0.0f;
            #pragma unroll
            for (int an = 0; an < 8; an++) {
                int c = bn + nb + an * 8 + (lane & 3) * 2;
                float e0 = ex2(acc[am][an][half * 2 + 0] * sc);
                float e1 = ex2(acc[am][an][half * 2 + 1] * sc);
                __half2 hv = __floats2half2_rn(e0, e1);
                *(__half2*)&Ez[(size_t)m * T_SEQ + c] = hv;
                float2 qv = __half22float2(hv);
                rs += qv.x + qv.y;
            }
            rs += __shfl_xor_sync(0xffffffffu, rs, 1);
            rs += __shfl_xor_sync(0xffffffffu, rs, 2);
            if ((lane & 3) == 0)
                psum[((size_t)z * T_SEQ + m) * 32 + blockIdx.x * 2 + nwarp] = rs;
        }
}

/* ---------------- fused psum-reduce + normalize + attn write + P@V --------
 * P fp16 [t][t], V fp16 transposed [d][t]: both feed m16n8k16 directly.
 */
__global__ __launch_bounds__(256, 3) void attn_pv_kernel(
    const __half* __restrict__ expS, const __half* __restrict__ Vt,
    const float* __restrict__ psum, float* __restrict__ attn,
    __half* __restrict__ ctxh)
{
    constexpr int SW   = 36;                   /* words per row */
    constexpr int P_W  = 64 * SW;              /* 2304 */
    constexpr int V_W  = 64 * SW;              /* 2304 */
    constexpr int STG  = P_W + V_W;            /* 4608 */
    extern __shared__ uint32_t smh[];
    float* invs = (float*)(smh + 2 * STG);

    const int tid = threadIdx.x;
    const int lane = tid & 31, wid = tid >> 5;
    const int r0 = lane >> 2;
    const int bm = blockIdx.x * 64;
    const int z = blockIdx.y;
    expS += (size_t)z * T_SEQ * T_SEQ;
    Vt   += (size_t)z * D_KK * T_SEQ;
    attn += (size_t)z * T_SEQ * T_SEQ;

    auto issue = [&](int k0, int st) {
        __half* Ph = (__half*)(smh + st * STG);
        __half* Vs = (__half*)(smh + st * STG + P_W);
        #pragma unroll
        for (int i = 0; i < 2; i++) {
            int f = tid + i * 256;
            int m = f >> 3, k8 = (f & 7) * 8;
            cp16(&Ph[m * 72 + k8], &expS[(size_t)(bm + m) * T_SEQ + k0 + k8]);
        }
        #pragma unroll
        for (int i = 0; i < 2; i++) {
            int f = tid + i * 256;
            int d = f >> 3, k8 = (f & 7) * 8;
            cp16(&Vs[d * 72 + k8], &Vt[(size_t)d * T_SEQ + k0 + k8]);
        }
        asm volatile("cp.async.commit_group;" ::: "memory");
    };

    issue(0, 0);

    if (tid < 64) {
        const float4* p = (const float4*)(psum + ((size_t)z * T_SEQ + bm + tid) * 32);
        float s = 0.0f;
        #pragma unroll
        for (int i = 0; i < 8; i++) {
            float4 v = p[i];
            s += v.x + v.y + v.z + v.w;
        }
        invs[tid] = 1.0f / s;
    }
    __syncthreads();

    const int mb = (wid & 1) * 32;
    const int nb = (wid >> 1) * 16;

    float acc[2][2][4];
    #pragma unroll
    for (int i = 0; i < 2; i++)
        #pragma unroll
        for (int j = 0; j < 2; j++)
            #pragma unroll
            for (int r = 0; r < 4; r++) acc[i][j][r] = 0.0f;

    const int nIter = T_SEQ / 64;   /* 32 */
    for (int it = 0; it < nIter; it++) {
        if (it + 1 < nIter) {
            issue((it + 1) * 64, (it + 1) & 1);
            asm volatile("cp.async.wait_group 1;" ::: "memory");
        } else {
            asm volatile("cp.async.wait_group 0;" ::: "memory");
        }
        __syncthreads();

        const uint32_t* P2 = smh + (it & 1) * STG;
        const uint32_t* V2 = P2 + P_W;

        #pragma unroll
        for (int ks = 0; ks < 4; ks++) {
            uint32_t af[2][4], bf[2][2];
            #pragma unroll
            for (int am = 0; am < 2; am++)
                #pragma unroll
                for (int j = 0; j < 4; j++)
                    af[am][j] = P2[(mb + am * 16 + r0 + (j & 1) * 8) * SW
                                   + ks * 8 + (lane & 3) + (j >> 1) * 4];
            #pragma unroll
            for (int an = 0; an < 2; an++)
                #pragma unroll
                for (int j = 0; j < 2; j++)
                    bf[an][j] = V2[(nb + an * 8 + r0) * SW
                                   + ks * 8 + (lane & 3) + j * 4];
            #pragma unroll
            for (int am = 0; am < 2; am++)
                #pragma unroll
                for (int an = 0; an < 2; an++)
                    mma16h(acc[am][an], af[am][0], af[am][1], af[am][2], af[am][3],
                           bf[an][0], bf[an][1]);
        }

        /* normalized attn write: fp16 smem -> fp32 gmem (coalesced) */
        #pragma unroll
        for (int i = 0; i < 8; i++) {
            int idx = tid + i * 256;
            int m = idx >> 5, c2 = idx & 31;
            uint32_t u = P2[m * SW + c2];
            float2 fv = __half22float2(*reinterpret_cast<__half2*>(&u));
            float iv = invs[m];
            fv.x *= iv; fv.y *= iv;
            *(float2*)&attn[(size_t)(bm + m) * T_SEQ + it * 64 + c2 * 2] = fv;
        }
        __syncthreads();
    }

    const int b = z >> 3, h = z & 7;
    __half* Cz = ctxh + (size_t)b * T_SEQ * D_MODEL + h * D_KK;
    #pragma unroll
    for (int am = 0; am < 2; am++)
        #pragma unroll
        for (int an = 0; an < 2; an++)
            #pragma unroll
            for (int half = 0; half < 2; half++) {
                int mr = mb + am * 16 + r0 + half * 8;
                int c = nb + an * 8 + (lane & 3) * 2;
                float iv = invs[mr];
                *(__half2*)&Cz[(size_t)(bm + mr) * D_MODEL + c]
                    = __floats2half2_rn(acc[am][an][half * 2 + 0] * iv,
                                        acc[am][an][half * 2 + 1] * iv);
            }
}

/* ---------------- fused residual add + LayerNorm ------------------------- */
template <int WRITE_H>
__global__ __launch_bounds__(128) void add_ln_kernel(
    const float* __restrict__ X, const float* __restrict__ Y,
    const float* __restrict__ g, const float* __restrict__ b,
    float* __restrict__ O, __half* __restrict__ Oh)
{
    const int tid = threadIdx.x;
    const size_t base = (size_t)blockIdx.x * D_MODEL + tid * 4;
    float4 xv = *(const float4*)&X[base];
    float4 yv = *(const float4*)&Y[base];
    float4 v = make_float4(xv.x + yv.x, xv.y + yv.y, xv.z + yv.z, xv.w + yv.w);

    float s  = v.x + v.y + v.z + v.w;
    float ss = v.x * v.x + v.y * v.y + v.z * v.z + v.w * v.w;
    s = warp_sum(s);
    ss = warp_sum(ss);

    __shared__ float r1[4], r2[4];
    const int wid = tid >> 5, lane = tid & 31;
    if (lane == 0) { r1[wid] = s; r2[wid] = ss; }
    __syncthreads();
    if (tid == 0) {
        float a = 0.0f, c = 0.0f;
        #pragma unroll
        for (int i = 0; i < 4; i++) { a += r1[i]; c += r2[i]; }
        r1[0] = a; r2[0] = c;
    }
    __syncthreads();
    const float mu  = r1[0] * (1.0f / 512.0f);
    const float var = r2[0] * (1.0f / 512.0f) - mu * mu;
    const float rs  = rsqrtf(var + 1e-5f);

    float4 gv = *(const float4*)&g[tid * 4];
    float4 bv = *(const float4*)&b[tid * 4];
    float4 o;
    o.x = (v.x - mu) * rs * gv.x + bv.x;
    o.y = (v.y - mu) * rs * gv.y + bv.y;
    o.z = (v.z - mu) * rs * gv.z + bv.z;
    o.w = (v.w - mu) * rs * gv.w + bv.w;
    *(float4*)&O[base] = o;
    if (WRITE_H) {
        ((__half2*)Oh)[base / 2]     = __floats2half2_rn(o.x, o.y);
        ((__half2*)Oh)[base / 2 + 1] = __floats2half2_rn(o.z, o.w);
    }
}

/* ---------------- launch -------------------------------------------------- */
#define SMEM_G64    30720   /* 2*(64*20 + 128*20)*4 */
#define SMEM_G128   40960   /* 2*(128*20 + 128*20)*4 */
#define SMEM_SCORES 36864   /* 2*128*36*4 */
#define SMEM_PV     37120   /* (2*4608 + 64)*4 */

extern "C" void kernel_launch(void* const* d_in, const int* in_sizes, int n_in,
                              void* d_out, int out_size)
{
    const float* x     = (const float*)d_in[0];
    const float* wq_w  = (const float*)d_in[1];
    const float* wq_b  = (const float*)d_in[2];
    const float* wk_w  = (const float*)d_in[3];
    const float* wk_b  = (const float*)d_in[4];
    const float* wv_w  = (const float*)d_in[5];
    const float* wv_b  = (const float*)d_in[6];
    const float* wo_w  = (const float*)d_in[7];
    const float* wo_b  = (const float*)d_in[8];
    const float* ln1_g = (const float*)d_in[9];
    const float* ln1_b = (const float*)d_in[10];
    const float* fc1_w = (const float*)d_in[11];
    const float* fc1_b = (const float*)d_in[12];
    const float* fc2_w = (const float*)d_in[13];
    const float* fc2_b = (const float*)d_in[14];
    const float* ln2_g = (const float*)d_in[15];
    const float* ln2_b = (const float*)d_in[16];

    float* out = (float*)d_out;

    __half *pxh, *pqh, *pkh, *pvth, *pctxh, *phh, *pffn1h, *pexp;
    __half *pwqt, *pwkt, *pwvt, *pwot, *pfc1t, *pfc2t;
    float *ptmp, *ph, *ppsum;
    cudaGetSymbolAddress((void**)&pxh,    g_xh);
    cudaGetSymbolAddress((void**)&pqh,    g_qh);
    cudaGetSymbolAddress((void**)&pkh,    g_kh);
    cudaGetSymbolAddress((void**)&pvth,   g_vth);
    cudaGetSymbolAddress((void**)&pctxh,  g_ctxh);
    cudaGetSymbolAddress((void**)&phh,    g_hh);
    cudaGetSymbolAddress((void**)&pffn1h, g_ffn1h);
    cudaGetSymbolAddress((void**)&pwqt,   g_wqt);
    cudaGetSymbolAddress((void**)&pwkt,   g_wkt);
    cudaGetSymbolAddress((void**)&pwvt,   g_wvt);
    cudaGetSymbolAddress((void**)&pwot,   g_wot);
    cudaGetSymbolAddress((void**)&pfc1t,  g_fc1t);
    cudaGetSymbolAddress((void**)&pfc2t,  g_fc2t);
    cudaGetSymbolAddress((void**)&ptmp,   g_tmp);
    cudaGetSymbolAddress((void**)&ph,     g_h);
    cudaGetSymbolAddress((void**)&ppsum,  g_psum);
    cudaGetSymbolAddress((void**)&pexp,   g_expS);

    float* attn;
    if ((size_t)out_size >= OUT_ELEMS + ATTN_ELEMS) {
        attn = out + OUT_ELEMS;
    } else {
        cudaGetSymbolAddress((void**)&attn, g_attn_scratch);
    }

    /* converts: x -> fp16; weights -> transposed fp16 */
    f2h_kernel<<<(BT * D_MODEL) / 512, 256>>>(x, pxh);
    transpose_h<<<dim3(16, 16), 256>>>(wq_w, pwqt, D_MODEL, D_MODEL);
    transpose_h<<<dim3(16, 16), 256>>>(wk_w, pwkt, D_MODEL, D_MODEL);
    transpose_h<<<dim3(16, 16), 256>>>(wv_w, pwvt, D_MODEL, D_MODEL);
    transpose_h<<<dim3(16, 16), 256>>>(wo_w, pwot, D_MODEL, D_MODEL);
    transpose_h<<<dim3(64, 16), 256>>>(fc1_w, pfc1t, D_MODEL, D_FF);
    transpose_h<<<dim3(16, 64), 256>>>(fc2_w, pfc2t, D_FF, D_MODEL);

    /* QKV: one launch; q/k fp16 [t][d], v fp16 transposed [d][t] */
    mma_gemm_h<64, EPI_QKV><<<dim3(4, 64, 3), 256, SMEM_G64>>>(
        pxh, pwqt, pwkt, pwvt, wq_b, wk_b, wv_b,
        pqh, pkh, pvth, D_MODEL, D_MODEL, D_MODEL, D_MODEL);

    /* scores: fp16 Q,K -> fp16 expS + psums */
    scores_kernel<<<dim3(16, 16, BH), 256, SMEM_SCORES>>>(pqh, pkh, pexp, ppsum);

    /* psum reduce + normalize + attn write + ctx(fp16) = P @ V */
    attn_pv_kernel<<<dim3(T_SEQ / 64, BH), 256, SMEM_PV>>>(
        pexp, pvth, ppsum, attn, pctxh);

    /* output projection + LN1 (h fp32 + fp16) */
    mma_gemm_h<64, EPI_BIAS><<<dim3(4, 64, 1), 256, SMEM_G64>>>(
        pctxh, pwot, pwot, pwot, wo_b, wo_b, wo_b,
        ptmp, ptmp, ptmp, D_MODEL, D_MODEL, D_MODEL, D_MODEL);
    add_ln_kernel<1><<<BT, 128>>>(x, ptmp, ln1_g, ln1_b, ph, phh);

    /* FFN + LN2 */
    mma_gemm_h<128, EPI_RELU_H><<<dim3(16, 32, 1), 256, SMEM_G128>>>(
        phh, pfc1t, pfc1t, pfc1t, fc1_b, fc1_b, fc1_b,
        pffn1h, pffn1h, pffn1h, D_MODEL, D_MODEL, D_MODEL, D_FF);
    mma_gemm_h<64, EPI_BIAS><<<dim3(4, 64, 1), 256, SMEM_G64>>>(
        pffn1h, pfc2t, pfc2t, pfc2t, fc2_b, fc2_b, fc2_b,
        ptmp, ptmp, ptmp, D_FF, D_FF, D_FF, D_MODEL);
    add_ln_kernel<0><<<BT, 128>>>(ph, ptmp, ln2_g, ln2_b, out, nullptr);
}

// round 17
// speedup vs baseline: 2.4397x; 1.0246x over previous
#include <cuda_runtime.h>
#include <cuda_fp16.h>
#include <math.h>
#include <stdint.h>

#define D_MODEL 512
#define N_HEADS 8
#define D_KK    64
#define D_FF    2048
#define T_SEQ   2048
#define B_BATCH 2
#define BT      (B_BATCH * T_SEQ)
#define BH      (B_BATCH * N_HEADS)

#define OUT_ELEMS  ((size_t)BT * D_MODEL)
#define ATTN_ELEMS ((size_t)BH * T_SEQ * T_SEQ)

#define EPI_BIAS   0   /* fp32 out */
#define EPI_RELU_H 1   /* relu, fp16 out */
#define EPI_QKV    2   /* q/k fp16 [t][d]; v fp16 [d][t] */

#define LOG2E 1.4426950408889634f

/* ---------------- scratch ------------------------------------------------- */
__device__ __half g_xh[BT * D_MODEL];
__device__ __half g_qh[BH * T_SEQ * D_KK];
__device__ __half g_kh[BH * T_SEQ * D_KK];
__device__ __half g_vth[BH * D_KK * T_SEQ];          /* V transposed [d][t] */
__device__ __half g_ctxh[BT * D_MODEL];
__device__ __half g_hh[BT * D_MODEL];
__device__ __half g_ffn1h[BT * D_FF];
__device__ __half g_wqt[D_MODEL * D_MODEL];
__device__ __half g_wkt[D_MODEL * D_MODEL];
__device__ __half g_wvt[D_MODEL * D_MODEL];
__device__ __half g_wot[D_MODEL * D_MODEL];
__device__ __half g_fc1t[D_FF * D_MODEL];            /* [N=2048][K=512] */
__device__ __half g_fc2t[D_MODEL * D_FF];            /* [N=512][K=2048] */
__device__ float  g_tmp[BT * D_MODEL];
__device__ float  g_h[BT * D_MODEL];
__device__ float  g_psum[(size_t)BH * T_SEQ * 32];
__device__ __half g_expS[(size_t)BH * T_SEQ * T_SEQ];
__device__ float  g_attn_scratch[BH * (size_t)T_SEQ * T_SEQ];

/* ---------------- helpers ------------------------------------------------- */
__device__ __forceinline__ float ex2(float x) {
    float r;
    asm("ex2.approx.f32 %0, %1;" : "=f"(r) : "f"(x));
    return r;
}
__device__ __forceinline__ void mma16h(float c[4], uint32_t a0, uint32_t a1,
                                       uint32_t a2, uint32_t a3,
                                       uint32_t b0, uint32_t b1) {
    asm volatile(
        "mma.sync.aligned.m16n8k16.row.col.f32.f16.f16.f32 "
        "{%0,%1,%2,%3}, {%4,%5,%6,%7}, {%8,%9}, {%0,%1,%2,%3};"
        : "+f"(c[0]), "+f"(c[1]), "+f"(c[2]), "+f"(c[3])
        : "r"(a0), "r"(a1), "r"(a2), "r"(a3), "r"(b0), "r"(b1));
}
__device__ __forceinline__ void cp16(void* sdst, const void* gsrc) {
    uint32_t s = (uint32_t)__cvta_generic_to_shared(sdst);
    asm volatile("cp.async.cg.shared.global [%0], [%1], 16;" :: "r"(s), "l"(gsrc));
}
__device__ __forceinline__ float warp_sum(float v) {
    #pragma unroll
    for (int o = 16; o > 0; o >>= 1) v += __shfl_xor_sync(0xffffffffu, v, o);
    return v;
}

/* ---------------- converts ------------------------------------------------ */
__global__ __launch_bounds__(256) void f2h_kernel(
    const float* __restrict__ s, __half* __restrict__ d)
{
    int i = blockIdx.x * 256 + threadIdx.x;
    float2 v = ((const float2*)s)[i];
    ((__half2*)d)[i] = __floats2half2_rn(v.x, v.y);
}

/* 64x64-tile transpose: W [K][N] fp32 -> Wt [N][K] fp16.
 * z (when BATCH4) selects one of four 512x512 weights. float4 loads,
 * half2 stores, 16 elems/thread.
 */
template <int BATCH4>
__global__ __launch_bounds__(256) void transpose_h(
    const float* __restrict__ W0, const float* __restrict__ W1,
    const float* __restrict__ W2, const float* __restrict__ W3,
    __half* __restrict__ T0, __half* __restrict__ T1,
    __half* __restrict__ T2, __half* __restrict__ T3,
    int K, int N)
{
    __shared__ float t[64][65];
    const float* W;
    __half* Wt;
    if (BATCH4) {
        int z = blockIdx.z;
        W  = (z == 0) ? W0 : (z == 1) ? W1 : (z == 2) ? W2 : W3;
        Wt = (z == 0) ? T0 : (z == 1) ? T1 : (z == 2) ? T2 : T3;
    } else { W = W0; Wt = T0; }

    const int n0 = blockIdx.x * 64, k0 = blockIdx.y * 64;
    const int tid = threadIdx.x;
    const int tx = tid & 15, ty = tid >> 4;   /* 16 x 16 */

    #pragma unroll
    for (int i = 0; i < 4; i++) {
        float4 v = *(const float4*)&W[(size_t)(k0 + ty + i * 16) * N + n0 + tx * 4];
        t[ty + i * 16][tx * 4 + 0] = v.x;
        t[ty + i * 16][tx * 4 + 1] = v.y;
        t[ty + i * 16][tx * 4 + 2] = v.z;
        t[ty + i * 16][tx * 4 + 3] = v.w;
    }
    __syncthreads();

    const int cx = tid & 31, cy = tid >> 5;   /* 32 x 8 */
    #pragma unroll
    for (int i = 0; i < 8; i++) {
        int n = cy + i * 8, k = cx * 2;
        *(__half2*)&Wt[(size_t)(n0 + n) * K + k0 + k]
            = __floats2half2_rn(t[k][n], t[k + 1][n]);
    }
}

/* ---------------- fp16 cp.async double-buffered GEMM ---------------------- */
template <int BM, int EPI>
__global__ __launch_bounds__(256, (BM == 64) ? 3 : 2) void mma_gemm_h(
    const __half* __restrict__ A,
    const __half* __restrict__ B0, const __half* __restrict__ B1, const __half* __restrict__ B2,
    const float* __restrict__ bias0, const float* __restrict__ bias1, const float* __restrict__ bias2,
    void* __restrict__ C0, void* __restrict__ C1, void* __restrict__ C2,
    int K, int lda, int ldb, int ldc)
{
    constexpr int SW  = 20;                    /* words per smem row */
    constexpr int A_W = BM * SW;
    constexpr int B_W = 128 * SW;
    constexpr int STG = A_W + B_W;
    constexpr int AN  = (BM == 128) ? 8 : 4;

    extern __shared__ uint32_t smh[];

    const int tid = threadIdx.x;
    const int lane = tid & 31, wid = tid >> 5;
    const int r0 = lane >> 2;
    const int z = blockIdx.z;
    const __half* B   = (z == 0) ? B0 : (z == 1) ? B1 : B2;
    const float* bias = (z == 0) ? bias0 : (z == 1) ? bias1 : bias2;
    void* C           = (z == 0) ? C0 : (z == 1) ? C1 : C2;

    const int bm = blockIdx.y * BM;
    const int bn = blockIdx.x * 128;
    const int mb = (BM == 128) ? (wid & 3) * 32 : (wid & 1) * 32;
    const int nb = (BM == 128) ? (wid >> 2) * 64 : (wid >> 1) * 32;

    float acc[2][AN][4];
    #pragma unroll
    for (int i = 0; i < 2; i++)
        #pragma unroll
        for (int j = 0; j < AN; j++)
            #pragma unroll
            for (int r = 0; r < 4; r++) acc[i][j][r] = 0.0f;

    auto issue = [&](int k0, int st) {
        __half* Ah = (__half*)(smh + st * STG);
        __half* Bh = (__half*)(smh + st * STG + A_W);
        #pragma unroll
        for (int i = 0; i < BM * 4 / 256; i++) {
            int f = tid + i * 256;
            int m = f >> 2, k8 = (f & 3) * 8;
            cp16(&Ah[m * 40 + k8], &A[(size_t)(bm + m) * lda + k0 + k8]);
        }
        #pragma unroll
        for (int i = 0; i < 2; i++) {
            int f = tid + i * 256;
            int n = f >> 2, k8 = (f & 3) * 8;
            cp16(&Bh[n * 40 + k8], &B[(size_t)(bn + n) * ldb + k0 + k8]);
        }
        asm volatile("cp.async.commit_group;" ::: "memory");
    };

    issue(0, 0);
    const int nIter = K / 32;
    for (int it = 0; it < nIter; it++) {
        if (it + 1 < nIter) {
            issue((it + 1) * 32, (it + 1) & 1);
            asm volatile("cp.async.wait_group 1;" ::: "memory");
        } else {
            asm volatile("cp.async.wait_group 0;" ::: "memory");
        }
        __syncthreads();

        const uint32_t* A2 = smh + (it & 1) * STG;
        const uint32_t* B2 = A2 + A_W;
        #pragma unroll
        for (int ks = 0; ks < 2; ks++) {
            uint32_t af[2][4], bf[AN][2];
            #pragma unroll
            for (int am = 0; am < 2; am++)
                #pragma unroll
                for (int j = 0; j < 4; j++)
                    af[am][j] = A2[(mb + am * 16 + r0 + (j & 1) * 8) * SW
                                   + ks * 8 + (lane & 3) + (j >> 1) * 4];
            #pragma unroll
            for (int an = 0; an < AN; an++)
                #pragma unroll
                for (int j = 0; j < 2; j++)
                    bf[an][j] = B2[(nb + an * 8 + r0) * SW
                                   + ks * 8 + (lane & 3) + j * 4];
            #pragma unroll
            for (int am = 0; am < 2; am++)
                #pragma unroll
                for (int an = 0; an < AN; an++)
                    mma16h(acc[am][an], af[am][0], af[am][1], af[am][2], af[am][3],
                           bf[an][0], bf[an][1]);
        }
        __syncthreads();
    }

    #pragma unroll
    for (int am = 0; am < 2; am++)
        #pragma unroll
        for (int an = 0; an < AN; an++)
            #pragma unroll
            for (int half = 0; half < 2; half++) {
                int m = bm + mb + am * 16 + r0 + half * 8;
                int c = bn + nb + an * 8 + (lane & 3) * 2;
                float v0 = acc[am][an][half * 2 + 0] + bias[c];
                float v1 = acc[am][an][half * 2 + 1] + bias[c + 1];
                if (EPI == EPI_BIAS) {
                    *(float2*)&((float*)C)[(size_t)m * ldc + c] = make_float2(v0, v1);
                } else if (EPI == EPI_RELU_H) {
                    v0 = fmaxf(v0, 0.0f); v1 = fmaxf(v1, 0.0f);
                    *(__half2*)&((__half*)C)[(size_t)m * ldc + c]
                        = __floats2half2_rn(v0, v1);
                } else { /* EPI_QKV */
                    int bb = m >> 11, t = m & (T_SEQ - 1);
                    int hh = c >> 6, d = c & (D_KK - 1);
                    __half* Ch = (__half*)C;
                    if (z < 2) {
                        *(__half2*)&Ch[((size_t)((bb * N_HEADS + hh) * T_SEQ) + t) * D_KK + d]
                            = __floats2half2_rn(v0, v1);
                    } else { /* V transposed [d][t] */
                        size_t base = (size_t)((bb * N_HEADS + hh) * D_KK);
                        Ch[(base + d) * T_SEQ + t]     = __float2half_rn(v0);
                        Ch[(base + d + 1) * T_SEQ + t] = __float2half_rn(v1);
                    }
                }
            }
}

/* ---------------- scores: expS(fp16) <- exp2(QK^T * sc), psums ------------ */
__global__ __launch_bounds__(256) void scores_kernel(
    const __half* __restrict__ Q, const __half* __restrict__ K,
    __half* __restrict__ expS, float* __restrict__ psum)
{
    constexpr int SW = 36;
    extern __shared__ uint32_t smh[];
    uint32_t* Q2 = smh;
    uint32_t* K2 = smh + 128 * SW;

    const int tid = threadIdx.x;
    const int lane = tid & 31, wid = tid >> 5;
    const int r0 = lane >> 2;
    const int z = blockIdx.z;
    const int bm = blockIdx.y * 128;
    const int bn = blockIdx.x * 128;
    Q += (size_t)z * T_SEQ * D_KK;
    K += (size_t)z * T_SEQ * D_KK;

    #pragma unroll
    for (int i = 0; i < 4; i++) {
        int f = tid + i * 256;
        int m = f >> 3, k8 = (f & 7) * 8;
        cp16((__half*)Q2 + m * 72 + k8, &Q[(size_t)(bm + m) * D_KK + k8]);
        cp16((__half*)K2 + m * 72 + k8, &K[(size_t)(bn + m) * D_KK + k8]);
    }
    asm volatile("cp.async.commit_group;" ::: "memory");
    asm volatile("cp.async.wait_group 0;" ::: "memory");
    __syncthreads();

    const int mb = (wid & 3) * 32;
    const int nwarp = wid >> 2;
    const int nb = nwarp * 64;

    float acc[2][8][4];
    #pragma unroll
    for (int i = 0; i < 2; i++)
        #pragma unroll
        for (int j = 0; j < 8; j++)
            #pragma unroll
            for (int r = 0; r < 4; r++) acc[i][j][r] = 0.0f;

    #pragma unroll
    for (int ks = 0; ks < 4; ks++) {
        uint32_t af[2][4], bf[8][2];
        #pragma unroll
        for (int am = 0; am < 2; am++)
            #pragma unroll
            for (int j = 0; j < 4; j++)
                af[am][j] = Q2[(mb + am * 16 + r0 + (j & 1) * 8) * SW
                               + ks * 8 + (lane & 3) + (j >> 1) * 4];
        #pragma unroll
        for (int an = 0; an < 8; an++)
            #pragma unroll
            for (int j = 0; j < 2; j++)
                bf[an][j] = K2[(nb + an * 8 + r0) * SW
                               + ks * 8 + (lane & 3) + j * 4];
        #pragma unroll
        for (int am = 0; am < 2; am++)
            #pragma unroll
            for (int an = 0; an < 8; an++)
                mma16h(acc[am][an], af[am][0], af[am][1], af[am][2], af[am][3],
                       bf[an][0], bf[an][1]);
    }

    const float sc = 0.125f * LOG2E;
    __half* Ez = expS + (size_t)z * T_SEQ * T_SEQ;
    #pragma unroll
    for (int am = 0; am < 2; am++)
        #pragma unroll
        for (int half = 0; half < 2; half++) {
            int m = bm + mb + r0 + am * 16 + half * 8;
            float rs = 0.0f;
            #pragma unroll
            for (int an = 0; an < 8; an++) {
                int c = bn + nb + an * 8 + (lane & 3) * 2;
                float e0 = ex2(acc[am][an][half * 2 + 0] * sc);
                float e1 = ex2(acc[am][an][half * 2 + 1] * sc);
                __half2 hv = __floats2half2_rn(e0, e1);
                *(__half2*)&Ez[(size_t)m * T_SEQ + c] = hv;
                float2 qv = __half22float2(hv);
                rs += qv.x + qv.y;
            }
            rs += __shfl_xor_sync(0xffffffffu, rs, 1);
            rs += __shfl_xor_sync(0xffffffffu, rs, 2);
            if ((lane & 3) == 0)
                psum[((size_t)z * T_SEQ + m) * 32 + blockIdx.x * 2 + nwarp] = rs;
        }
}

/* ---------------- fused psum-reduce + normalize + attn write + P@V -------- */
__global__ __launch_bounds__(256, 3) void attn_pv_kernel(
    const __half* __restrict__ expS, const __half* __restrict__ Vt,
    const float* __restrict__ psum, float* __restrict__ attn,
    __half* __restrict__ ctxh)
{
    constexpr int SW   = 36;
    constexpr int P_W  = 64 * SW;
    constexpr int V_W  = 64 * SW;
    constexpr int STG  = P_W + V_W;
    extern __shared__ uint32_t smh[];
    float* invs = (float*)(smh + 2 * STG);

    const int tid = threadIdx.x;
    const int lane = tid & 31, wid = tid >> 5;
    const int r0 = lane >> 2;
    const int bm = blockIdx.x * 64;
    const int z = blockIdx.y;
    expS += (size_t)z * T_SEQ * T_SEQ;
    Vt   += (size_t)z * D_KK * T_SEQ;
    attn += (size_t)z * T_SEQ * T_SEQ;

    auto issue = [&](int k0, int st) {
        __half* Ph = (__half*)(smh + st * STG);
        __half* Vs = (__half*)(smh + st * STG + P_W);
        #pragma unroll
        for (int i = 0; i < 2; i++) {
            int f = tid + i * 256;
            int m = f >> 3, k8 = (f & 7) * 8;
            cp16(&Ph[m * 72 + k8], &expS[(size_t)(bm + m) * T_SEQ + k0 + k8]);
        }
        #pragma unroll
        for (int i = 0; i < 2; i++) {
            int f = tid + i * 256;
            int d = f >> 3, k8 = (f & 7) * 8;
            cp16(&Vs[d * 72 + k8], &Vt[(size_t)d * T_SEQ + k0 + k8]);
        }
        asm volatile("cp.async.commit_group;" ::: "memory");
    };

    issue(0, 0);

    if (tid < 64) {
        const float4* p = (const float4*)(psum + ((size_t)z * T_SEQ + bm + tid) * 32);
        float s = 0.0f;
        #pragma unroll
        for (int i = 0; i < 8; i++) {
            float4 v = p[i];
            s += v.x + v.y + v.z + v.w;
        }
        invs[tid] = 1.0f / s;
    }
    __syncthreads();

    const int mb = (wid & 1) * 32;
    const int nb = (wid >> 1) * 16;

    float acc[2][2][4];
    #pragma unroll
    for (int i = 0; i < 2; i++)
        #pragma unroll
        for (int j = 0; j < 2; j++)
            #pragma unroll
            for (int r = 0; r < 4; r++) acc[i][j][r] = 0.0f;

    const int nIter = T_SEQ / 64;   /* 32 */
    for (int it = 0; it < nIter; it++) {
        if (it + 1 < nIter) {
            issue((it + 1) * 64, (it + 1) & 1);
            asm volatile("cp.async.wait_group 1;" ::: "memory");
        } else {
            asm volatile("cp.async.wait_group 0;" ::: "memory");
        }
        __syncthreads();

        const uint32_t* P2 = smh + (it & 1) * STG;
        const uint32_t* V2 = P2 + P_W;

        #pragma unroll
        for (int ks = 0; ks < 4; ks++) {
            uint32_t af[2][4], bf[2][2];
            #pragma unroll
            for (int am = 0; am < 2; am++)
                #pragma unroll
                for (int j = 0; j < 4; j++)
                    af[am][j] = P2[(mb + am * 16 + r0 + (j & 1) * 8) * SW
                                   + ks * 8 + (lane & 3) + (j >> 1) * 4];
            #pragma unroll
            for (int an = 0; an < 2; an++)
                #pragma unroll
                for (int j = 0; j < 2; j++)
                    bf[an][j] = V2[(nb + an * 8 + r0) * SW
                                   + ks * 8 + (lane & 3) + j * 4];
            #pragma unroll
            for (int am = 0; am < 2; am++)
                #pragma unroll
                for (int an = 0; an < 2; an++)
                    mma16h(acc[am][an], af[am][0], af[am][1], af[am][2], af[am][3],
                           bf[an][0], bf[an][1]);
        }

        /* normalized attn write: fp16 smem -> fp32 gmem (coalesced) */
        #pragma unroll
        for (int i = 0; i < 8; i++) {
            int idx = tid + i * 256;
            int m = idx >> 5, c2 = idx & 31;
            uint32_t u = P2[m * SW + c2];
            float2 fv = __half22float2(*reinterpret_cast<__half2*>(&u));
            float iv = invs[m];
            fv.x *= iv; fv.y *= iv;
            *(float2*)&attn[(size_t)(bm + m) * T_SEQ + it * 64 + c2 * 2] = fv;
        }
        __syncthreads();
    }

    const int b = z >> 3, h = z & 7;
    __half* Cz = ctxh + (size_t)b * T_SEQ * D_MODEL + h * D_KK;
    #pragma unroll
    for (int am = 0; am < 2; am++)
        #pragma unroll
        for (int an = 0; an < 2; an++)
            #pragma unroll
            for (int half = 0; half < 2; half++) {
                int mr = mb + am * 16 + r0 + half * 8;
                int c = nb + an * 8 + (lane & 3) * 2;
                float iv = invs[mr];
                *(__half2*)&Cz[(size_t)(bm + mr) * D_MODEL + c]
                    = __floats2half2_rn(acc[am][an][half * 2 + 0] * iv,
                                        acc[am][an][half * 2 + 1] * iv);
            }
}

/* ---------------- fused residual add + LayerNorm ------------------------- */
template <int WRITE_H>
__global__ __launch_bounds__(128) void add_ln_kernel(
    const float* __restrict__ X, const float* __restrict__ Y,
    const float* __restrict__ g, const float* __restrict__ b,
    float* __restrict__ O, __half* __restrict__ Oh)
{
    const int tid = threadIdx.x;
    const size_t base = (size_t)blockIdx.x * D_MODEL + tid * 4;
    float4 xv = *(const float4*)&X[base];
    float4 yv = *(const float4*)&Y[base];
    float4 v = make_float4(xv.x + yv.x, xv.y + yv.y, xv.z + yv.z, xv.w + yv.w);

    float s  = v.x + v.y + v.z + v.w;
    float ss = v.x * v.x + v.y * v.y + v.z * v.z + v.w * v.w;
    s = warp_sum(s);
    ss = warp_sum(ss);

    __shared__ float r1[4], r2[4];
    const int wid = tid >> 5, lane = tid & 31;
    if (lane == 0) { r1[wid] = s; r2[wid] = ss; }
    __syncthreads();
    if (tid == 0) {
        float a = 0.0f, c = 0.0f;
        #pragma unroll
        for (int i = 0; i < 4; i++) { a += r1[i]; c += r2[i]; }
        r1[0] = a; r2[0] = c;
    }
    __syncthreads();
    const float mu  = r1[0] * (1.0f / 512.0f);
    const float var = r2[0] * (1.0f / 512.0f) - mu * mu;
    const float rs  = rsqrtf(var + 1e-5f);

    float4 gv = *(const float4*)&g[tid * 4];
    float4 bv = *(const float4*)&b[tid * 4];
    float4 o;
    o.x = (v.x - mu) * rs * gv.x + bv.x;
    o.y = (v.y - mu) * rs * gv.y + bv.y;
    o.z = (v.z - mu) * rs * gv.z + bv.z;
    o.w = (v.w - mu) * rs * gv.w + bv.w;
    *(float4*)&O[base] = o;
    if (WRITE_H) {
        ((__half2*)Oh)[base / 2]     = __floats2half2_rn(o.x, o.y);
        ((__half2*)Oh)[base / 2 + 1] = __floats2half2_rn(o.z, o.w);
    }
}

/* ---------------- launch -------------------------------------------------- */
#define SMEM_G64    30720
#define SMEM_G128   40960
#define SMEM_SCORES 36864
#define SMEM_PV     37120

extern "C" void kernel_launch(void* const* d_in, const int* in_sizes, int n_in,
                              void* d_out, int out_size)
{
    const float* x     = (const float*)d_in[0];
    const float* wq_w  = (const float*)d_in[1];
    const float* wq_b  = (const float*)d_in[2];
    const float* wk_w  = (const float*)d_in[3];
    const float* wk_b  = (const float*)d_in[4];
    const float* wv_w  = (const float*)d_in[5];
    const float* wv_b  = (const float*)d_in[6];
    const float* wo_w  = (const float*)d_in[7];
    const float* wo_b  = (const float*)d_in[8];
    const float* ln1_g = (const float*)d_in[9];
    const float* ln1_b = (const float*)d_in[10];
    const float* fc1_w = (const float*)d_in[11];
    const float* fc1_b = (const float*)d_in[12];
    const float* fc2_w = (const float*)d_in[13];
    const float* fc2_b = (const float*)d_in[14];
    const float* ln2_g = (const float*)d_in[15];
    const float* ln2_b = (const float*)d_in[16];

    float* out = (float*)d_out;

    __half *pxh, *pqh, *pkh, *pvth, *pctxh, *phh, *pffn1h, *pexp;
    __half *pwqt, *pwkt, *pwvt, *pwot, *pfc1t, *pfc2t;
    float *ptmp, *ph, *ppsum;
    cudaGetSymbolAddress((void**)&pxh,    g_xh);
    cudaGetSymbolAddress((void**)&pqh,    g_qh);
    cudaGetSymbolAddress((void**)&pkh,    g_kh);
    cudaGetSymbolAddress((void**)&pvth,   g_vth);
    cudaGetSymbolAddress((void**)&pctxh,  g_ctxh);
    cudaGetSymbolAddress((void**)&phh,    g_hh);
    cudaGetSymbolAddress((void**)&pffn1h, g_ffn1h);
    cudaGetSymbolAddress((void**)&pwqt,   g_wqt);
    cudaGetSymbolAddress((void**)&pwkt,   g_wkt);
    cudaGetSymbolAddress((void**)&pwvt,   g_wvt);
    cudaGetSymbolAddress((void**)&pwot,   g_wot);
    cudaGetSymbolAddress((void**)&pfc1t,  g_fc1t);
    cudaGetSymbolAddress((void**)&pfc2t,  g_fc2t);
    cudaGetSymbolAddress((void**)&ptmp,   g_tmp);
    cudaGetSymbolAddress((void**)&ph,     g_h);
    cudaGetSymbolAddress((void**)&ppsum,  g_psum);
    cudaGetSymbolAddress((void**)&pexp,   g_expS);

    float* attn;
    if ((size_t)out_size >= OUT_ELEMS + ATTN_ELEMS) {
        attn = out + OUT_ELEMS;
    } else {
        cudaGetSymbolAddress((void**)&attn, g_attn_scratch);
    }

    /* converts: x -> fp16; weights -> transposed fp16 (3 launches) */
    f2h_kernel<<<(BT * D_MODEL) / 512, 256>>>(x, pxh);
    transpose_h<1><<<dim3(8, 8, 4), 256>>>(
        wq_w, wk_w, wv_w, wo_w, pwqt, pwkt, pwvt, pwot, D_MODEL, D_MODEL);
    transpose_h<0><<<dim3(32, 8), 256>>>(
        fc1_w, nullptr, nullptr, nullptr, pfc1t, nullptr, nullptr, nullptr,
        D_MODEL, D_FF);
    transpose_h<0><<<dim3(8, 32), 256>>>(
        fc2_w, nullptr, nullptr, nullptr, pfc2t, nullptr, nullptr, nullptr,
        D_FF, D_MODEL);

    /* QKV: one launch; q/k fp16 [t][d], v fp16 transposed [d][t] */
    mma_gemm_h<64, EPI_QKV><<<dim3(4, 64, 3), 256, SMEM_G64>>>(
        pxh, pwqt, pwkt, pwvt, wq_b, wk_b, wv_b,
        pqh, pkh, pvth, D_MODEL, D_MODEL, D_MODEL, D_MODEL);

    /* scores: fp16 Q,K -> fp16 expS + psums */
    scores_kernel<<<dim3(16, 16, BH), 256, SMEM_SCORES>>>(pqh, pkh, pexp, ppsum);

    /* psum reduce + normalize + attn write + ctx(fp16) = P @ V */
    attn_pv_kernel<<<dim3(T_SEQ / 64, BH), 256, SMEM_PV>>>(
        pexp, pvth, ppsum, attn, pctxh);

    /* output projection + LN1 */
    mma_gemm_h<64, EPI_BIAS><<<dim3(4, 64, 1), 256, SMEM_G64>>>(
        pctxh, pwot, pwot, pwot, wo_b, wo_b, wo_b,
        ptmp, ptmp, ptmp, D_MODEL, D_MODEL, D_MODEL, D_MODEL);
    add_ln_kernel<1><<<BT, 128>>>(x, ptmp, ln1_g, ln1_b, ph, phh);

    /* FFN + LN2 */
    mma_gemm_h<128, EPI_RELU_H><<<dim3(16, 32, 1), 256, SMEM_G128>>>(
        phh, pfc1t, pfc1t, pfc1t, fc1_b, fc1_b, fc1_b,
        pffn1h, pffn1h, pffn1h, D_MODEL, D_MODEL, D_MODEL, D_FF);
    mma_gemm_h<64, EPI_BIAS><<<dim3(4, 64, 1), 256, SMEM_G64>>>(
        pffn1h, pfc2t, pfc2t, pfc2t, fc2_b, fc2_b, fc2_b,
        ptmp, ptmp, ptmp, D_FF, D_FF, D_FF, D_MODEL);
    add_ln_kernel<0><<<BT, 128>>>(ph, ptmp, ln2_g, ln2_b, out, nullptr);
}